// round 10
// baseline (speedup 1.0000x reference)
#include <cuda_runtime.h>
#include <cuda_fp16.h>
#include <math.h>
#include <stdint.h>
#include <stddef.h>

#define B_  2
#define N_  4096
#define C_  1024
#define H_  16
#define D_  64
#define BH_ (B_*H_)

// ---------------- scratch (device globals; no allocs allowed) ----------------
__device__ __half g_xh    [(size_t)B_*N_*C_];     // x in fp16
__device__ __half g_wqkv_h[(size_t)3*C_*C_];      // qkv_w fp16
__device__ __half g_wproj_h[(size_t)C_*C_];       // proj_w fp16
__device__ __half g_q [(size_t)BH_*N_*D_];        // LN'd, pre-scaled by 0.125*log2e
__device__ __half g_k [(size_t)BH_*N_*D_];
__device__ __half g_v [(size_t)BH_*N_*D_];
__device__ __half g_ao[(size_t)B_*N_*C_];         // [B,N,C] attention out fp16

// ---------------- helpers ----------------
__device__ __forceinline__ uint32_t packh2(float x, float y) {
    __half2 h = __floats2half2_rn(x, y);
    return *(uint32_t*)&h;
}
__device__ __forceinline__ uint32_t saddr(const void* p) {
    return (uint32_t)__cvta_generic_to_shared(p);
}

__device__ __forceinline__ void mma16(float* c, const uint32_t* a, const uint32_t* b) {
    asm volatile(
        "mma.sync.aligned.m16n8k16.row.col.f32.f16.f16.f32 "
        "{%0,%1,%2,%3}, {%4,%5,%6,%7}, {%8,%9}, {%0,%1,%2,%3};"
        : "+f"(c[0]), "+f"(c[1]), "+f"(c[2]), "+f"(c[3])
        : "r"(a[0]), "r"(a[1]), "r"(a[2]), "r"(a[3]), "r"(b[0]), "r"(b[1]));
}

#define LDSM_X4(R0,R1,R2,R3,ADDR) \
    asm volatile("ldmatrix.sync.aligned.m8n8.x4.shared.b16 {%0,%1,%2,%3}, [%4];" \
        : "=r"(R0), "=r"(R1), "=r"(R2), "=r"(R3) : "r"(ADDR))
#define LDSM_X4T(R0,R1,R2,R3,ADDR) \
    asm volatile("ldmatrix.sync.aligned.m8n8.x4.trans.shared.b16 {%0,%1,%2,%3}, [%4];" \
        : "=r"(R0), "=r"(R1), "=r"(R2), "=r"(R3) : "r"(ADDR))

#define CP_ASYNC16(dst_u32, src) \
    asm volatile("cp.async.cg.shared.global [%0], [%1], 16;" :: "r"(dst_u32), "l"(src))
#define CP_COMMIT() asm volatile("cp.async.commit_group;")
#define CP_WAIT(n)  asm volatile("cp.async.wait_group %0;" :: "n"(n))

// =============================================================================
// fp32 -> fp16 elementwise convert
// =============================================================================
__global__ __launch_bounds__(256) void f2h_kernel(const float* __restrict__ in,
                                                  __half* __restrict__ out, int n4)
{
    int i = blockIdx.x * blockDim.x + threadIdx.x;
    if (i >= n4) return;
    float4 v = ((const float4*)in)[i];
    ((uint2*)out)[i] = make_uint2(packh2(v.x, v.y), packh2(v.z, v.w));
}

#define GST 40

// =============================================================================
// QKV GEMM with fused bias + per-head LayerNorm epilogue (proven R9).
// =============================================================================
__global__ __launch_bounds__(256, 2) void gemm_qkv_ln(
    const __half* __restrict__ A, const __half* __restrict__ W,
    const float* __restrict__ bias,
    const float* __restrict__ qw, const float* __restrict__ qb,
    const float* __restrict__ kw, const float* __restrict__ kb,
    __half* __restrict__ Qo, __half* __restrict__ Ko, __half* __restrict__ Vo)
{
    extern __shared__ __half sg[];
    __half* As = sg;
    __half* Bs = sg + 3 * 128 * GST;

    const int K = C_;
    const int tid  = threadIdx.x;
    const int warp = tid >> 5, lane = tid & 31;
    const int mw   = warp >> 1, nw = warp & 1;      // 4 x 2 warp grid
    const int g    = lane >> 2, tg = lane & 3;
    const int bm   = blockIdx.y * 128, bn = blockIdx.x * 128;

    const int aR = (lane & 7) + ((lane >> 3) & 1) * 8;
    const int aC = (lane >> 4) * 8;
    const int bR = (lane & 7) + (lane >> 4) * 8;
    const int bC = ((lane >> 3) & 1) * 8;

    const int lrow = tid >> 2;
    const int lc8  = (tid & 3) * 8;

    const __half* Ap = A + (size_t)(bm + lrow) * K + lc8;
    const __half* Wp = W + (size_t)(bn + lrow) * K + lc8;

    const int T = K / 32;

    auto issue = [&](int it) {
        const int st = it % 3;
        __half* as = As + st * 128 * GST;
        __half* bs = Bs + st * 128 * GST;
        CP_ASYNC16(saddr(&as[lrow * GST + lc8]),        Ap + it * 32);
        CP_ASYNC16(saddr(&as[(lrow + 64) * GST + lc8]), Ap + (size_t)64 * K + it * 32);
        CP_ASYNC16(saddr(&bs[lrow * GST + lc8]),        Wp + it * 32);
        CP_ASYNC16(saddr(&bs[(lrow + 64) * GST + lc8]), Wp + (size_t)64 * K + it * 32);
        CP_COMMIT();
    };

    float acc[2][8][4];
    #pragma unroll
    for (int i = 0; i < 2; i++)
        #pragma unroll
        for (int j = 0; j < 8; j++)
            #pragma unroll
            for (int e = 0; e < 4; e++) acc[i][j][e] = 0.f;

    issue(0);
    issue(1);

    for (int it = 0; it < T; it++) {
        if (it < T - 1) { CP_WAIT(1); } else { CP_WAIT(0); }
        __syncthreads();
        if (it + 2 < T) issue(it + 2);

        const int st = it % 3;
        __half* as = As + st * 128 * GST;
        __half* bs = Bs + st * 128 * GST;

        #pragma unroll
        for (int ks = 0; ks < 2; ks++) {
            const int kk = ks * 16;
            uint32_t a[2][4], b[8][2];
            #pragma unroll
            for (int mt = 0; mt < 2; mt++)
                LDSM_X4(a[mt][0], a[mt][1], a[mt][2], a[mt][3],
                        saddr(&as[(mw * 32 + mt * 16 + aR) * GST + kk + aC]));
            #pragma unroll
            for (int np = 0; np < 4; np++) {
                uint32_t r0, r1, r2, r3;
                LDSM_X4(r0, r1, r2, r3,
                        saddr(&bs[(nw * 64 + np * 16 + bR) * GST + kk + bC]));
                b[2*np][0] = r0; b[2*np][1] = r1;
                b[2*np+1][0] = r2; b[2*np+1][1] = r3;
            }
            #pragma unroll
            for (int mt = 0; mt < 2; mt++)
                #pragma unroll
                for (int nt = 0; nt < 8; nt++)
                    mma16(acc[mt][nt], a[mt], b[nt]);
        }
    }

    const int cn0 = bn + nw * 64;
    const int sec = cn0 >> 10;             // 0=q, 1=k, 2=v
    const int h   = (cn0 >> 6) & 15;

    float bz[16];
    #pragma unroll
    for (int nt = 0; nt < 8; nt++) {
        bz[2*nt]   = bias[cn0 + nt*8 + 2*tg];
        bz[2*nt+1] = bias[cn0 + nt*8 + 2*tg + 1];
    }
    float lnw[16], lnb[16];
    if (sec < 2) {
        const float* ws = (sec == 0) ? qw : kw;
        const float* bs2 = (sec == 0) ? qb : kb;
        #pragma unroll
        for (int nt = 0; nt < 8; nt++) {
            lnw[2*nt]   = ws[nt*8 + 2*tg];
            lnw[2*nt+1] = ws[nt*8 + 2*tg + 1];
            lnb[2*nt]   = bs2[nt*8 + 2*tg];
            lnb[2*nt+1] = bs2[nt*8 + 2*tg + 1];
        }
    }
    __half* dst = (sec == 0) ? Qo : (sec == 1) ? Ko : Vo;
    const float osc = (sec == 0) ? 0.125f * 1.44269504f : 1.0f;
    const float inv64 = 1.f / 64.f;

    #pragma unroll
    for (int mt = 0; mt < 2; mt++) {
        #pragma unroll
        for (int hh = 0; hh < 2; hh++) {
            const int grow = bm + mw * 32 + mt * 16 + hh * 8 + g;
            float v[16];
            float s = 0.f, ss = 0.f;
            #pragma unroll
            for (int nt = 0; nt < 8; nt++) {
                v[2*nt]   = acc[mt][nt][2*hh]     + bz[2*nt];
                v[2*nt+1] = acc[mt][nt][2*hh + 1] + bz[2*nt+1];
                s  += v[2*nt] + v[2*nt+1];
                ss += v[2*nt]*v[2*nt] + v[2*nt+1]*v[2*nt+1];
            }
            uint32_t outv[8];
            if (sec < 2) {
                s  += __shfl_xor_sync(0xffffffffu, s, 1);
                s  += __shfl_xor_sync(0xffffffffu, s, 2);
                ss += __shfl_xor_sync(0xffffffffu, ss, 1);
                ss += __shfl_xor_sync(0xffffffffu, ss, 2);
                const float mu = s * inv64;
                const float var = fmaxf(ss * inv64 - mu * mu, 0.f);
                const float rstd = rsqrtf(var + 1e-5f);
                #pragma unroll
                for (int nt = 0; nt < 8; nt++) {
                    float o0 = ((v[2*nt]   - mu) * rstd * lnw[2*nt]   + lnb[2*nt])   * osc;
                    float o1 = ((v[2*nt+1] - mu) * rstd * lnw[2*nt+1] + lnb[2*nt+1]) * osc;
                    outv[nt] = packh2(o0, o1);
                }
            } else {
                #pragma unroll
                for (int nt = 0; nt < 8; nt++)
                    outv[nt] = packh2(v[2*nt], v[2*nt+1]);
            }
            const int bb = grow >> 12, n = grow & (N_ - 1);
            __half* op = dst + ((size_t)((bb * H_ + h) * N_) + n) * D_ + 2 * tg;
            #pragma unroll
            for (int nt = 0; nt < 8; nt++)
                *(uint32_t*)(op + nt * 8) = outv[nt];
        }
    }
}

// =============================================================================
// fp16 GEMM (proven R6) for the output projection.
// =============================================================================
__global__ __launch_bounds__(256, 2) void gemm_h16(
    const __half* __restrict__ A, const __half* __restrict__ W,
    const float* __restrict__ bias, float* __restrict__ Cmat,
    int M, int Nout, int K)
{
    extern __shared__ __half sg[];
    __half* As = sg;
    __half* Bs = sg + 3 * 128 * GST;

    const int tid  = threadIdx.x;
    const int warp = tid >> 5, lane = tid & 31;
    const int mw   = warp >> 2, nw = warp & 3;
    const int g    = lane >> 2, tg = lane & 3;
    const int bm   = blockIdx.y * 128, bn = blockIdx.x * 128;

    const int aR = (lane & 7) + ((lane >> 3) & 1) * 8;
    const int aC = (lane >> 4) * 8;
    const int bR = (lane & 7) + (lane >> 4) * 8;
    const int bC = ((lane >> 3) & 1) * 8;

    const int lrow = tid >> 2;
    const int lc8  = (tid & 3) * 8;

    const __half* Ap = A + (size_t)(bm + lrow) * K + lc8;
    const __half* Wp = W + (size_t)(bn + lrow) * K + lc8;

    const int T = K / 32;

    auto issue = [&](int it) {
        const int st = it % 3;
        __half* as = As + st * 128 * GST;
        __half* bs = Bs + st * 128 * GST;
        CP_ASYNC16(saddr(&as[lrow * GST + lc8]),        Ap + it * 32);
        CP_ASYNC16(saddr(&as[(lrow + 64) * GST + lc8]), Ap + (size_t)64 * K + it * 32);
        CP_ASYNC16(saddr(&bs[lrow * GST + lc8]),        Wp + it * 32);
        CP_ASYNC16(saddr(&bs[(lrow + 64) * GST + lc8]), Wp + (size_t)64 * K + it * 32);
        CP_COMMIT();
    };

    float acc[4][4][4];
    #pragma unroll
    for (int i = 0; i < 4; i++)
        #pragma unroll
        for (int j = 0; j < 4; j++)
            #pragma unroll
            for (int e = 0; e < 4; e++) acc[i][j][e] = 0.f;

    issue(0);
    issue(1);

    for (int it = 0; it < T; it++) {
        if (it < T - 1) { CP_WAIT(1); } else { CP_WAIT(0); }
        __syncthreads();
        if (it + 2 < T) issue(it + 2);

        const int st = it % 3;
        __half* as = As + st * 128 * GST;
        __half* bs = Bs + st * 128 * GST;

        #pragma unroll
        for (int ks = 0; ks < 2; ks++) {
            const int kk = ks * 16;
            uint32_t a[4][4], b[4][2];
            #pragma unroll
            for (int mt = 0; mt < 4; mt++)
                LDSM_X4(a[mt][0], a[mt][1], a[mt][2], a[mt][3],
                        saddr(&as[(mw * 64 + mt * 16 + aR) * GST + kk + aC]));
            #pragma unroll
            for (int np = 0; np < 2; np++) {
                uint32_t r0, r1, r2, r3;
                LDSM_X4(r0, r1, r2, r3,
                        saddr(&bs[(nw * 32 + np * 16 + bR) * GST + kk + bC]));
                b[2*np][0] = r0; b[2*np][1] = r1;
                b[2*np+1][0] = r2; b[2*np+1][1] = r3;
            }
            #pragma unroll
            for (int mt = 0; mt < 4; mt++)
                #pragma unroll
                for (int nt = 0; nt < 4; nt++)
                    mma16(acc[mt][nt], a[mt], b[nt]);
        }
    }

    #pragma unroll
    for (int mt = 0; mt < 4; mt++) {
        const int row0 = bm + mw * 64 + mt * 16 + g;
        #pragma unroll
        for (int nt = 0; nt < 4; nt++) {
            const int col = bn + nw * 32 + nt * 8 + 2 * tg;
            const float b0 = bias[col], b1 = bias[col + 1];
            *(float2*)(Cmat + (size_t)row0 * Nout + col) =
                make_float2(acc[mt][nt][0] + b0, acc[mt][nt][1] + b1);
            *(float2*)(Cmat + (size_t)(row0 + 8) * Nout + col) =
                make_float2(acc[mt][nt][2] + b0, acc[mt][nt][3] + b1);
        }
    }
}

// =============================================================================
// Flash attention: 256 q-rows/CTA, 512 threads (16 warps x 16 rows).
// Halves K/V L2 traffic vs the 128-row tile. No-max softmax (ex2.f16x2),
// l via ones-MMA. 1 CTA/SM (92KB smem).
// =============================================================================
#define AST2 72

__global__ __launch_bounds__(512, 1) void attn_h16(
    const __half* __restrict__ Q, const __half* __restrict__ Kg,
    const __half* __restrict__ Vg, __half* __restrict__ AO)
{
    extern __shared__ __half sh[];
    __half* Qs = sh;                      // [256][AST2]
    __half* Ks = Qs + 256 * AST2;         // [3][64][AST2]
    __half* Vs = Ks + 3 * 64 * AST2;      // [3][64][AST2]

    const int tid  = threadIdx.x;
    const int warp = tid >> 5, lane = tid & 31;
    const int g    = lane >> 2, tg = lane & 3;
    const int bh   = blockIdx.y;
    const int q0   = blockIdx.x * 256;
    const int mrow = warp * 16;

    const int aR = (lane & 7) + ((lane >> 3) & 1) * 8;
    const int aC = (lane >> 4) * 8;
    const int bR = (lane & 7) + (lane >> 4) * 8;
    const int bC = ((lane >> 3) & 1) * 8;

    const __half* Qb = Q  + ((size_t)bh * N_ + q0) * D_;
    const __half* Kb = Kg + (size_t)bh * N_ * D_;
    const __half* Vb = Vg + (size_t)bh * N_ * D_;

    // ---- load Q tile (256x64 halves): 2048 uint4 chunks over 512 threads ----
    #pragma unroll
    for (int j = 0; j < 4; j++) {
        const int id  = tid + 512 * j;
        const int row = id >> 3;
        const int c8  = (id & 7) * 8;
        *(uint4*)&Qs[row * AST2 + c8] = *(const uint4*)(Qb + (size_t)row * D_ + c8);
    }

    // K/V tile: 512 chunks per tensor -> exactly one chunk per thread
    const int lrow = tid >> 3;            // 0..63
    const int lc8  = (tid & 7) * 8;       // 0..56

    auto issueKV = [&](int t) {
        const int st = t % 3;
        CP_ASYNC16(saddr(&Ks[(st * 64 + lrow) * AST2 + lc8]),
                   Kb + (size_t)(t * 64 + lrow) * D_ + lc8);
        CP_ASYNC16(saddr(&Vs[(st * 64 + lrow) * AST2 + lc8]),
                   Vb + (size_t)(t * 64 + lrow) * D_ + lc8);
        CP_COMMIT();
    };

    issueKV(0);
    issueKV(1);
    __syncthreads();

    uint32_t qf[4][4];
    #pragma unroll
    for (int ks = 0; ks < 4; ks++)
        LDSM_X4(qf[ks][0], qf[ks][1], qf[ks][2], qf[ks][3],
                saddr(&Qs[(mrow + aR) * AST2 + ks * 16 + aC]));

    float o[8][4];
    #pragma unroll
    for (int nt = 0; nt < 8; nt++)
        #pragma unroll
        for (int e = 0; e < 4; e++) o[nt][e] = 0.f;
    float lacc[4] = { 0.f, 0.f, 0.f, 0.f };
    const uint32_t bones[2] = { 0x3C003C00u, 0x3C003C00u };

    const int T = N_ / 64;
    for (int t = 0; t < T; t++) {
        if (t < T - 1) { CP_WAIT(1); } else { CP_WAIT(0); }
        __syncthreads();
        if (t + 2 < T) issueKV(t + 2);

        const int st = t % 3;
        const __half* Kc = Ks + st * 64 * AST2;
        const __half* Vc = Vs + st * 64 * AST2;

        // ---- S = Q @ K^T ----
        float sacc[8][4];
        #pragma unroll
        for (int nt = 0; nt < 8; nt++)
            #pragma unroll
            for (int e = 0; e < 4; e++) sacc[nt][e] = 0.f;

        #pragma unroll
        for (int ks = 0; ks < 4; ks++) {
            const int kk = ks * 16;
            #pragma unroll
            for (int np = 0; np < 4; np++) {
                uint32_t r0, r1, r2, r3;
                LDSM_X4(r0, r1, r2, r3,
                        saddr(&Kc[(np * 16 + bR) * AST2 + kk + bC]));
                uint32_t b0[2] = { r0, r1 }, b1[2] = { r2, r3 };
                mma16(sacc[2*np],     qf[ks], b0);
                mma16(sacc[2*np + 1], qf[ks], b1);
            }
        }

        // ---- p = exp2(s) in f16x2 ----
        uint32_t ph[8][2];
        #pragma unroll
        for (int nt = 0; nt < 8; nt++) {
            uint32_t lo = packh2(sacc[nt][0], sacc[nt][1]);
            uint32_t hi = packh2(sacc[nt][2], sacc[nt][3]);
            asm("ex2.approx.f16x2 %0, %1;" : "=r"(ph[nt][0]) : "r"(lo));
            asm("ex2.approx.f16x2 %0, %1;" : "=r"(ph[nt][1]) : "r"(hi));
        }

        // ---- O += P @ V ; l += P @ ones ----
        #pragma unroll
        for (int ks = 0; ks < 4; ks++) {
            const int kk = ks * 16;
            uint32_t a[4] = { ph[2*ks][0], ph[2*ks][1], ph[2*ks+1][0], ph[2*ks+1][1] };
            mma16(lacc, a, bones);
            #pragma unroll
            for (int dp = 0; dp < 4; dp++) {
                uint32_t r0, r1, r2, r3;
                LDSM_X4T(r0, r1, r2, r3,
                         saddr(&Vc[(kk + aR) * AST2 + dp * 16 + aC]));
                uint32_t b0[2] = { r0, r1 }, b1[2] = { r2, r3 };
                mma16(o[2*dp],     a, b0);
                mma16(o[2*dp + 1], a, b1);
            }
        }
    }

    // ---- epilogue ----
    const float inv0 = 1.f / lacc[0], inv1 = 1.f / lacc[2];

    const int b = bh >> 4, h = bh & 15;
    __half* op = AO + ((size_t)(b * N_ + q0 + mrow + g)) * C_ + h * D_;
    #pragma unroll
    for (int nt = 0; nt < 8; nt++) {
        const int col = nt * 8 + 2 * tg;
        *(__half2*)(op + col) = __floats2half2_rn(o[nt][0] * inv0, o[nt][1] * inv0);
        *(__half2*)(op + (size_t)8 * C_ + col) =
            __floats2half2_rn(o[nt][2] * inv1, o[nt][3] * inv1);
    }
}

// =============================================================================
extern "C" void kernel_launch(void* const* d_in, const int* in_sizes, int n_in,
                              void* d_out, int out_size)
{
    const float* x      = (const float*)d_in[0];
    const float* qkv_w  = (const float*)d_in[1];
    const float* qkv_b  = (const float*)d_in[2];
    const float* qnw    = (const float*)d_in[3];
    const float* qnb    = (const float*)d_in[4];
    const float* knw    = (const float*)d_in[5];
    const float* knb    = (const float*)d_in[6];
    const float* proj_w = (const float*)d_in[7];
    const float* proj_b = (const float*)d_in[8];
    float* out = (float*)d_out;

    __half *xh, *wqkv, *wproj, *q, *k, *v, *ao;
    cudaGetSymbolAddress((void**)&xh,    g_xh);
    cudaGetSymbolAddress((void**)&wqkv,  g_wqkv_h);
    cudaGetSymbolAddress((void**)&wproj, g_wproj_h);
    cudaGetSymbolAddress((void**)&q,     g_q);
    cudaGetSymbolAddress((void**)&k,     g_k);
    cudaGetSymbolAddress((void**)&v,     g_v);
    cudaGetSymbolAddress((void**)&ao,    g_ao);

    const int gemm_smem = 2 * 3 * 128 * GST * (int)sizeof(__half);     // 61440
    const int attn_smem = (256 + 6 * 64) * AST2 * (int)sizeof(__half); // 92160
    cudaFuncSetAttribute(gemm_h16, cudaFuncAttributeMaxDynamicSharedMemorySize, gemm_smem);
    cudaFuncSetAttribute(gemm_qkv_ln, cudaFuncAttributeMaxDynamicSharedMemorySize, gemm_smem);
    cudaFuncSetAttribute(attn_h16, cudaFuncAttributeMaxDynamicSharedMemorySize, attn_smem);

    // 0) fp16 preconversion
    {
        int n4x = (B_ * N_ * C_) / 4;
        f2h_kernel<<<(n4x + 255) / 256, 256>>>(x, xh, n4x);
        int n4w = (3 * C_ * C_) / 4;
        f2h_kernel<<<(n4w + 255) / 256, 256>>>(qkv_w, wqkv, n4w);
        int n4p = (C_ * C_) / 4;
        f2h_kernel<<<(n4p + 255) / 256, 256>>>(proj_w, wproj, n4p);
    }
    // 1) QKV projection + fused bias/LN/split
    {
        dim3 grid(3 * C_ / 128, (B_ * N_) / 128);
        gemm_qkv_ln<<<grid, 256, gemm_smem>>>(xh, wqkv, qkv_b,
                                              qnw, qnb, knw, knb, q, k, v);
    }
    // 2) attention (256-row Q tiles)
    {
        dim3 grid(N_ / 256, BH_);
        attn_h16<<<grid, 512, attn_smem>>>(q, k, v, ao);
    }
    // 3) output projection -> d_out
    {
        dim3 grid(C_ / 128, (B_ * N_) / 128);
        gemm_h16<<<grid, 256, gemm_smem>>>(ao, wproj, proj_b, out, B_ * N_, C_, C_);
    }
}

// round 11
// speedup vs baseline: 1.6141x; 1.6141x over previous
#include <cuda_runtime.h>
#include <cuda_fp16.h>
#include <math.h>
#include <stdint.h>
#include <stddef.h>

#define B_  2
#define N_  4096
#define C_  1024
#define H_  16
#define D_  64
#define BH_ (B_*H_)

// ---------------- scratch (device globals; no allocs allowed) ----------------
__device__ __half g_xh    [(size_t)B_*N_*C_];     // x in fp16
__device__ __half g_wqkv_h[(size_t)3*C_*C_];      // qkv_w fp16
__device__ __half g_wproj_h[(size_t)C_*C_];       // proj_w fp16
__device__ __half g_q [(size_t)BH_*N_*D_];        // LN'd, pre-scaled by 0.125*log2e
__device__ __half g_k [(size_t)BH_*N_*D_];
__device__ __half g_v [(size_t)BH_*N_*D_];
__device__ __half g_ao[(size_t)B_*N_*C_];         // [B,N,C] attention out fp16

// ---------------- helpers ----------------
__device__ __forceinline__ uint32_t packh2(float x, float y) {
    __half2 h = __floats2half2_rn(x, y);
    return *(uint32_t*)&h;
}
__device__ __forceinline__ uint32_t saddr(const void* p) {
    return (uint32_t)__cvta_generic_to_shared(p);
}

__device__ __forceinline__ void mma16(float* c, const uint32_t* a, const uint32_t* b) {
    asm volatile(
        "mma.sync.aligned.m16n8k16.row.col.f32.f16.f16.f32 "
        "{%0,%1,%2,%3}, {%4,%5,%6,%7}, {%8,%9}, {%0,%1,%2,%3};"
        : "+f"(c[0]), "+f"(c[1]), "+f"(c[2]), "+f"(c[3])
        : "r"(a[0]), "r"(a[1]), "r"(a[2]), "r"(a[3]), "r"(b[0]), "r"(b[1]));
}

#define LDSM_X4(R0,R1,R2,R3,ADDR) \
    asm volatile("ldmatrix.sync.aligned.m8n8.x4.shared.b16 {%0,%1,%2,%3}, [%4];" \
        : "=r"(R0), "=r"(R1), "=r"(R2), "=r"(R3) : "r"(ADDR))
#define LDSM_X4T(R0,R1,R2,R3,ADDR) \
    asm volatile("ldmatrix.sync.aligned.m8n8.x4.trans.shared.b16 {%0,%1,%2,%3}, [%4];" \
        : "=r"(R0), "=r"(R1), "=r"(R2), "=r"(R3) : "r"(ADDR))

#define CP_ASYNC16(dst_u32, src) \
    asm volatile("cp.async.cg.shared.global [%0], [%1], 16;" :: "r"(dst_u32), "l"(src))
#define CP_COMMIT() asm volatile("cp.async.commit_group;")
#define CP_WAIT(n)  asm volatile("cp.async.wait_group %0;" :: "n"(n))

// =============================================================================
// fp32 -> fp16 elementwise convert
// =============================================================================
__global__ __launch_bounds__(256) void f2h_kernel(const float* __restrict__ in,
                                                  __half* __restrict__ out, int n4)
{
    int i = blockIdx.x * blockDim.x + threadIdx.x;
    if (i >= n4) return;
    float4 v = ((const float4*)in)[i];
    ((uint2*)out)[i] = make_uint2(packh2(v.x, v.y), packh2(v.z, v.w));
}

#define GST 40

// =============================================================================
// QKV GEMM with fused bias + per-head LayerNorm epilogue (proven R9).
// =============================================================================
__global__ __launch_bounds__(256, 2) void gemm_qkv_ln(
    const __half* __restrict__ A, const __half* __restrict__ W,
    const float* __restrict__ bias,
    const float* __restrict__ qw, const float* __restrict__ qb,
    const float* __restrict__ kw, const float* __restrict__ kb,
    __half* __restrict__ Qo, __half* __restrict__ Ko, __half* __restrict__ Vo)
{
    extern __shared__ __half sg[];
    __half* As = sg;
    __half* Bs = sg + 3 * 128 * GST;

    const int K = C_;
    const int tid  = threadIdx.x;
    const int warp = tid >> 5, lane = tid & 31;
    const int mw   = warp >> 1, nw = warp & 1;      // 4 x 2 warp grid
    const int g    = lane >> 2, tg = lane & 3;
    const int bm   = blockIdx.y * 128, bn = blockIdx.x * 128;

    const int aR = (lane & 7) + ((lane >> 3) & 1) * 8;
    const int aC = (lane >> 4) * 8;
    const int bR = (lane & 7) + (lane >> 4) * 8;
    const int bC = ((lane >> 3) & 1) * 8;

    const int lrow = tid >> 2;
    const int lc8  = (tid & 3) * 8;

    const __half* Ap = A + (size_t)(bm + lrow) * K + lc8;
    const __half* Wp = W + (size_t)(bn + lrow) * K + lc8;

    const int T = K / 32;

    auto issue = [&](int it) {
        const int st = it % 3;
        __half* as = As + st * 128 * GST;
        __half* bs = Bs + st * 128 * GST;
        CP_ASYNC16(saddr(&as[lrow * GST + lc8]),        Ap + it * 32);
        CP_ASYNC16(saddr(&as[(lrow + 64) * GST + lc8]), Ap + (size_t)64 * K + it * 32);
        CP_ASYNC16(saddr(&bs[lrow * GST + lc8]),        Wp + it * 32);
        CP_ASYNC16(saddr(&bs[(lrow + 64) * GST + lc8]), Wp + (size_t)64 * K + it * 32);
        CP_COMMIT();
    };

    float acc[2][8][4];
    #pragma unroll
    for (int i = 0; i < 2; i++)
        #pragma unroll
        for (int j = 0; j < 8; j++)
            #pragma unroll
            for (int e = 0; e < 4; e++) acc[i][j][e] = 0.f;

    issue(0);
    issue(1);

    for (int it = 0; it < T; it++) {
        if (it < T - 1) { CP_WAIT(1); } else { CP_WAIT(0); }
        __syncthreads();
        if (it + 2 < T) issue(it + 2);

        const int st = it % 3;
        __half* as = As + st * 128 * GST;
        __half* bs = Bs + st * 128 * GST;

        #pragma unroll
        for (int ks = 0; ks < 2; ks++) {
            const int kk = ks * 16;
            uint32_t a[2][4], b[8][2];
            #pragma unroll
            for (int mt = 0; mt < 2; mt++)
                LDSM_X4(a[mt][0], a[mt][1], a[mt][2], a[mt][3],
                        saddr(&as[(mw * 32 + mt * 16 + aR) * GST + kk + aC]));
            #pragma unroll
            for (int np = 0; np < 4; np++) {
                uint32_t r0, r1, r2, r3;
                LDSM_X4(r0, r1, r2, r3,
                        saddr(&bs[(nw * 64 + np * 16 + bR) * GST + kk + bC]));
                b[2*np][0] = r0; b[2*np][1] = r1;
                b[2*np+1][0] = r2; b[2*np+1][1] = r3;
            }
            #pragma unroll
            for (int mt = 0; mt < 2; mt++)
                #pragma unroll
                for (int nt = 0; nt < 8; nt++)
                    mma16(acc[mt][nt], a[mt], b[nt]);
        }
    }

    const int cn0 = bn + nw * 64;
    const int sec = cn0 >> 10;             // 0=q, 1=k, 2=v
    const int h   = (cn0 >> 6) & 15;

    float bz[16];
    #pragma unroll
    for (int nt = 0; nt < 8; nt++) {
        bz[2*nt]   = bias[cn0 + nt*8 + 2*tg];
        bz[2*nt+1] = bias[cn0 + nt*8 + 2*tg + 1];
    }
    float lnw[16], lnb[16];
    if (sec < 2) {
        const float* ws = (sec == 0) ? qw : kw;
        const float* bs2 = (sec == 0) ? qb : kb;
        #pragma unroll
        for (int nt = 0; nt < 8; nt++) {
            lnw[2*nt]   = ws[nt*8 + 2*tg];
            lnw[2*nt+1] = ws[nt*8 + 2*tg + 1];
            lnb[2*nt]   = bs2[nt*8 + 2*tg];
            lnb[2*nt+1] = bs2[nt*8 + 2*tg + 1];
        }
    }
    __half* dst = (sec == 0) ? Qo : (sec == 1) ? Ko : Vo;
    const float osc = (sec == 0) ? 0.125f * 1.44269504f : 1.0f;
    const float inv64 = 1.f / 64.f;

    #pragma unroll
    for (int mt = 0; mt < 2; mt++) {
        #pragma unroll
        for (int hh = 0; hh < 2; hh++) {
            const int grow = bm + mw * 32 + mt * 16 + hh * 8 + g;
            float v[16];
            float s = 0.f, ss = 0.f;
            #pragma unroll
            for (int nt = 0; nt < 8; nt++) {
                v[2*nt]   = acc[mt][nt][2*hh]     + bz[2*nt];
                v[2*nt+1] = acc[mt][nt][2*hh + 1] + bz[2*nt+1];
                s  += v[2*nt] + v[2*nt+1];
                ss += v[2*nt]*v[2*nt] + v[2*nt+1]*v[2*nt+1];
            }
            uint32_t outv[8];
            if (sec < 2) {
                s  += __shfl_xor_sync(0xffffffffu, s, 1);
                s  += __shfl_xor_sync(0xffffffffu, s, 2);
                ss += __shfl_xor_sync(0xffffffffu, ss, 1);
                ss += __shfl_xor_sync(0xffffffffu, ss, 2);
                const float mu = s * inv64;
                const float var = fmaxf(ss * inv64 - mu * mu, 0.f);
                const float rstd = rsqrtf(var + 1e-5f);
                #pragma unroll
                for (int nt = 0; nt < 8; nt++) {
                    float o0 = ((v[2*nt]   - mu) * rstd * lnw[2*nt]   + lnb[2*nt])   * osc;
                    float o1 = ((v[2*nt+1] - mu) * rstd * lnw[2*nt+1] + lnb[2*nt+1]) * osc;
                    outv[nt] = packh2(o0, o1);
                }
            } else {
                #pragma unroll
                for (int nt = 0; nt < 8; nt++)
                    outv[nt] = packh2(v[2*nt], v[2*nt+1]);
            }
            const int bb = grow >> 12, n = grow & (N_ - 1);
            __half* op = dst + ((size_t)((bb * H_ + h) * N_) + n) * D_ + 2 * tg;
            #pragma unroll
            for (int nt = 0; nt < 8; nt++)
                *(uint32_t*)(op + nt * 8) = outv[nt];
        }
    }
}

// =============================================================================
// fp16 GEMM (proven R6) for the output projection.
// =============================================================================
__global__ __launch_bounds__(256, 2) void gemm_h16(
    const __half* __restrict__ A, const __half* __restrict__ W,
    const float* __restrict__ bias, float* __restrict__ Cmat,
    int M, int Nout, int K)
{
    extern __shared__ __half sg[];
    __half* As = sg;
    __half* Bs = sg + 3 * 128 * GST;

    const int tid  = threadIdx.x;
    const int warp = tid >> 5, lane = tid & 31;
    const int mw   = warp >> 2, nw = warp & 3;
    const int g    = lane >> 2, tg = lane & 3;
    const int bm   = blockIdx.y * 128, bn = blockIdx.x * 128;

    const int aR = (lane & 7) + ((lane >> 3) & 1) * 8;
    const int aC = (lane >> 4) * 8;
    const int bR = (lane & 7) + (lane >> 4) * 8;
    const int bC = ((lane >> 3) & 1) * 8;

    const int lrow = tid >> 2;
    const int lc8  = (tid & 3) * 8;

    const __half* Ap = A + (size_t)(bm + lrow) * K + lc8;
    const __half* Wp = W + (size_t)(bn + lrow) * K + lc8;

    const int T = K / 32;

    auto issue = [&](int it) {
        const int st = it % 3;
        __half* as = As + st * 128 * GST;
        __half* bs = Bs + st * 128 * GST;
        CP_ASYNC16(saddr(&as[lrow * GST + lc8]),        Ap + it * 32);
        CP_ASYNC16(saddr(&as[(lrow + 64) * GST + lc8]), Ap + (size_t)64 * K + it * 32);
        CP_ASYNC16(saddr(&bs[lrow * GST + lc8]),        Wp + it * 32);
        CP_ASYNC16(saddr(&bs[(lrow + 64) * GST + lc8]), Wp + (size_t)64 * K + it * 32);
        CP_COMMIT();
    };

    float acc[4][4][4];
    #pragma unroll
    for (int i = 0; i < 4; i++)
        #pragma unroll
        for (int j = 0; j < 4; j++)
            #pragma unroll
            for (int e = 0; e < 4; e++) acc[i][j][e] = 0.f;

    issue(0);
    issue(1);

    for (int it = 0; it < T; it++) {
        if (it < T - 1) { CP_WAIT(1); } else { CP_WAIT(0); }
        __syncthreads();
        if (it + 2 < T) issue(it + 2);

        const int st = it % 3;
        __half* as = As + st * 128 * GST;
        __half* bs = Bs + st * 128 * GST;

        #pragma unroll
        for (int ks = 0; ks < 2; ks++) {
            const int kk = ks * 16;
            uint32_t a[4][4], b[4][2];
            #pragma unroll
            for (int mt = 0; mt < 4; mt++)
                LDSM_X4(a[mt][0], a[mt][1], a[mt][2], a[mt][3],
                        saddr(&as[(mw * 64 + mt * 16 + aR) * GST + kk + aC]));
            #pragma unroll
            for (int np = 0; np < 2; np++) {
                uint32_t r0, r1, r2, r3;
                LDSM_X4(r0, r1, r2, r3,
                        saddr(&bs[(nw * 32 + np * 16 + bR) * GST + kk + bC]));
                b[2*np][0] = r0; b[2*np][1] = r1;
                b[2*np+1][0] = r2; b[2*np+1][1] = r3;
            }
            #pragma unroll
            for (int mt = 0; mt < 4; mt++)
                #pragma unroll
                for (int nt = 0; nt < 4; nt++)
                    mma16(acc[mt][nt], a[mt], b[nt]);
        }
    }

    #pragma unroll
    for (int mt = 0; mt < 4; mt++) {
        const int row0 = bm + mw * 64 + mt * 16 + g;
        #pragma unroll
        for (int nt = 0; nt < 4; nt++) {
            const int col = bn + nw * 32 + nt * 8 + 2 * tg;
            const float b0 = bias[col], b1 = bias[col + 1];
            *(float2*)(Cmat + (size_t)row0 * Nout + col) =
                make_float2(acc[mt][nt][0] + b0, acc[mt][nt][1] + b1);
            *(float2*)(Cmat + (size_t)(row0 + 8) * Nout + col) =
                make_float2(acc[mt][nt][2] + b0, acc[mt][nt][3] + b1);
        }
    }
}

// =============================================================================
// Flash attention (R9 config): 128 q-rows/CTA, 256 threads, 8 warps x 16 rows.
// 4-stage K/V cp.async pipeline (prefetch distance 3). No-max softmax
// (ex2.f16x2), l via ones-MMA. 2 CTAs/SM (92KB smem each).
// =============================================================================
#define AST2 72

__global__ __launch_bounds__(256, 2) void attn_h16(
    const __half* __restrict__ Q, const __half* __restrict__ Kg,
    const __half* __restrict__ Vg, __half* __restrict__ AO)
{
    extern __shared__ __half sh[];
    __half* Qs = sh;                      // [128][AST2]
    __half* Ks = Qs + 128 * AST2;         // [4][64][AST2]
    __half* Vs = Ks + 4 * 64 * AST2;      // [4][64][AST2]

    const int tid  = threadIdx.x;
    const int warp = tid >> 5, lane = tid & 31;
    const int g    = lane >> 2, tg = lane & 3;
    const int bh   = blockIdx.y;
    const int q0   = blockIdx.x * 128;
    const int mrow = warp * 16;

    const int aR = (lane & 7) + ((lane >> 3) & 1) * 8;
    const int aC = (lane >> 4) * 8;
    const int bR = (lane & 7) + (lane >> 4) * 8;
    const int bC = ((lane >> 3) & 1) * 8;

    const __half* Qb = Q  + ((size_t)bh * N_ + q0) * D_;
    const __half* Kb = Kg + (size_t)bh * N_ * D_;
    const __half* Vb = Vg + (size_t)bh * N_ * D_;

    #pragma unroll
    for (int j = 0; j < 4; j++) {
        const int id  = tid + 256 * j;
        const int row = id >> 3;
        const int c8  = (id & 7) * 8;
        *(uint4*)&Qs[row * AST2 + c8] = *(const uint4*)(Qb + (size_t)row * D_ + c8);
    }

    const int lrow = tid >> 2;
    const int lc8  = (tid & 3) * 8;

    auto issueKV = [&](int t) {
        const int st = t & 3;
        const __half* kp = Kb + (size_t)(t * 64 + lrow) * D_ + lc8;
        const __half* vp = Vb + (size_t)(t * 64 + lrow) * D_ + lc8;
        __half* ks = &Ks[(st * 64 + lrow) * AST2 + lc8];
        __half* vs = &Vs[(st * 64 + lrow) * AST2 + lc8];
        CP_ASYNC16(saddr(ks),      kp);
        CP_ASYNC16(saddr(ks + 32), kp + 32);
        CP_ASYNC16(saddr(vs),      vp);
        CP_ASYNC16(saddr(vs + 32), vp + 32);
        CP_COMMIT();
    };

    issueKV(0);
    issueKV(1);
    issueKV(2);
    __syncthreads();

    uint32_t qf[4][4];
    #pragma unroll
    for (int ks = 0; ks < 4; ks++)
        LDSM_X4(qf[ks][0], qf[ks][1], qf[ks][2], qf[ks][3],
                saddr(&Qs[(mrow + aR) * AST2 + ks * 16 + aC]));

    float o[8][4];
    #pragma unroll
    for (int nt = 0; nt < 8; nt++)
        #pragma unroll
        for (int e = 0; e < 4; e++) o[nt][e] = 0.f;
    float lacc[4] = { 0.f, 0.f, 0.f, 0.f };
    const uint32_t bones[2] = { 0x3C003C00u, 0x3C003C00u };

    const int T = N_ / 64;
    for (int t = 0; t < T; t++) {
        if (t < T - 2) { CP_WAIT(2); }
        else if (t < T - 1) { CP_WAIT(1); }
        else { CP_WAIT(0); }
        __syncthreads();
        if (t + 3 < T) issueKV(t + 3);

        const int st = t & 3;
        const __half* Kc = Ks + st * 64 * AST2;
        const __half* Vc = Vs + st * 64 * AST2;

        // ---- S = Q @ K^T ----
        float sacc[8][4];
        #pragma unroll
        for (int nt = 0; nt < 8; nt++)
            #pragma unroll
            for (int e = 0; e < 4; e++) sacc[nt][e] = 0.f;

        #pragma unroll
        for (int ks = 0; ks < 4; ks++) {
            const int kk = ks * 16;
            #pragma unroll
            for (int np = 0; np < 4; np++) {
                uint32_t r0, r1, r2, r3;
                LDSM_X4(r0, r1, r2, r3,
                        saddr(&Kc[(np * 16 + bR) * AST2 + kk + bC]));
                uint32_t b0[2] = { r0, r1 }, b1[2] = { r2, r3 };
                mma16(sacc[2*np],     qf[ks], b0);
                mma16(sacc[2*np + 1], qf[ks], b1);
            }
        }

        // ---- p = exp2(s) in f16x2 ----
        uint32_t ph[8][2];
        #pragma unroll
        for (int nt = 0; nt < 8; nt++) {
            uint32_t lo = packh2(sacc[nt][0], sacc[nt][1]);
            uint32_t hi = packh2(sacc[nt][2], sacc[nt][3]);
            asm("ex2.approx.f16x2 %0, %1;" : "=r"(ph[nt][0]) : "r"(lo));
            asm("ex2.approx.f16x2 %0, %1;" : "=r"(ph[nt][1]) : "r"(hi));
        }

        // ---- O += P @ V ; l += P @ ones ----
        #pragma unroll
        for (int ks = 0; ks < 4; ks++) {
            const int kk = ks * 16;
            uint32_t a[4] = { ph[2*ks][0], ph[2*ks][1], ph[2*ks+1][0], ph[2*ks+1][1] };
            mma16(lacc, a, bones);
            #pragma unroll
            for (int dp = 0; dp < 4; dp++) {
                uint32_t r0, r1, r2, r3;
                LDSM_X4T(r0, r1, r2, r3,
                         saddr(&Vc[(kk + aR) * AST2 + dp * 16 + aC]));
                uint32_t b0[2] = { r0, r1 }, b1[2] = { r2, r3 };
                mma16(o[2*dp],     a, b0);
                mma16(o[2*dp + 1], a, b1);
            }
        }
    }

    // ---- epilogue ----
    const float inv0 = 1.f / lacc[0], inv1 = 1.f / lacc[2];

    const int b = bh >> 4, h = bh & 15;
    __half* op = AO + ((size_t)(b * N_ + q0 + mrow + g)) * C_ + h * D_;
    #pragma unroll
    for (int nt = 0; nt < 8; nt++) {
        const int col = nt * 8 + 2 * tg;
        *(__half2*)(op + col) = __floats2half2_rn(o[nt][0] * inv0, o[nt][1] * inv0);
        *(__half2*)(op + (size_t)8 * C_ + col) =
            __floats2half2_rn(o[nt][2] * inv1, o[nt][3] * inv1);
    }
}

// =============================================================================
extern "C" void kernel_launch(void* const* d_in, const int* in_sizes, int n_in,
                              void* d_out, int out_size)
{
    const float* x      = (const float*)d_in[0];
    const float* qkv_w  = (const float*)d_in[1];
    const float* qkv_b  = (const float*)d_in[2];
    const float* qnw    = (const float*)d_in[3];
    const float* qnb    = (const float*)d_in[4];
    const float* knw    = (const float*)d_in[5];
    const float* knb    = (const float*)d_in[6];
    const float* proj_w = (const float*)d_in[7];
    const float* proj_b = (const float*)d_in[8];
    float* out = (float*)d_out;

    __half *xh, *wqkv, *wproj, *q, *k, *v, *ao;
    cudaGetSymbolAddress((void**)&xh,    g_xh);
    cudaGetSymbolAddress((void**)&wqkv,  g_wqkv_h);
    cudaGetSymbolAddress((void**)&wproj, g_wproj_h);
    cudaGetSymbolAddress((void**)&q,     g_q);
    cudaGetSymbolAddress((void**)&k,     g_k);
    cudaGetSymbolAddress((void**)&v,     g_v);
    cudaGetSymbolAddress((void**)&ao,    g_ao);

    const int gemm_smem = 2 * 3 * 128 * GST * (int)sizeof(__half);     // 61440
    const int attn_smem = (128 + 8 * 64) * AST2 * (int)sizeof(__half); // 92160
    cudaFuncSetAttribute(gemm_h16, cudaFuncAttributeMaxDynamicSharedMemorySize, gemm_smem);
    cudaFuncSetAttribute(gemm_qkv_ln, cudaFuncAttributeMaxDynamicSharedMemorySize, gemm_smem);
    cudaFuncSetAttribute(attn_h16, cudaFuncAttributeMaxDynamicSharedMemorySize, attn_smem);

    // 0) fp16 preconversion
    {
        int n4x = (B_ * N_ * C_) / 4;
        f2h_kernel<<<(n4x + 255) / 256, 256>>>(x, xh, n4x);
        int n4w = (3 * C_ * C_) / 4;
        f2h_kernel<<<(n4w + 255) / 256, 256>>>(qkv_w, wqkv, n4w);
        int n4p = (C_ * C_) / 4;
        f2h_kernel<<<(n4p + 255) / 256, 256>>>(proj_w, wproj, n4p);
    }
    // 1) QKV projection + fused bias/LN/split
    {
        dim3 grid(3 * C_ / 128, (B_ * N_) / 128);
        gemm_qkv_ln<<<grid, 256, gemm_smem>>>(xh, wqkv, qkv_b,
                                              qnw, qnb, knw, knb, q, k, v);
    }
    // 2) attention (128-row Q tiles, 4-stage K/V pipeline)
    {
        dim3 grid(N_ / 128, BH_);
        attn_h16<<<grid, 256, attn_smem>>>(q, k, v, ao);
    }
    // 3) output projection -> d_out
    {
        dim3 grid(C_ / 128, (B_ * N_) / 128);
        gemm_h16<<<grid, 256, gemm_smem>>>(ao, wproj, proj_b, out, B_ * N_, C_, C_);
    }
}

// round 12
// speedup vs baseline: 1.6418x; 1.0172x over previous
#include <cuda_runtime.h>
#include <cuda_fp16.h>
#include <math.h>
#include <stdint.h>
#include <stddef.h>

#define B_  2
#define N_  4096
#define C_  1024
#define H_  16
#define D_  64
#define BH_ (B_*H_)

// ---------------- scratch (device globals; no allocs allowed) ----------------
__device__ __half g_xh    [(size_t)B_*N_*C_];     // x in fp16
__device__ __half g_wqkv_h[(size_t)3*C_*C_];      // qkv_w fp16
__device__ __half g_wproj_h[(size_t)C_*C_];       // proj_w fp16
__device__ __half g_q [(size_t)BH_*N_*D_];        // LN'd, pre-scaled by 0.125*log2e
__device__ __half g_k [(size_t)BH_*N_*D_];
__device__ __half g_v [(size_t)BH_*N_*D_];
__device__ __half g_ao[(size_t)B_*N_*C_];         // [B,N,C] attention out fp16

// ---------------- helpers ----------------
__device__ __forceinline__ uint32_t packh2(float x, float y) {
    __half2 h = __floats2half2_rn(x, y);
    return *(uint32_t*)&h;
}
__device__ __forceinline__ uint32_t saddr(const void* p) {
    return (uint32_t)__cvta_generic_to_shared(p);
}

__device__ __forceinline__ void mma16(float* c, const uint32_t* a, const uint32_t* b) {
    asm volatile(
        "mma.sync.aligned.m16n8k16.row.col.f32.f16.f16.f32 "
        "{%0,%1,%2,%3}, {%4,%5,%6,%7}, {%8,%9}, {%0,%1,%2,%3};"
        : "+f"(c[0]), "+f"(c[1]), "+f"(c[2]), "+f"(c[3])
        : "r"(a[0]), "r"(a[1]), "r"(a[2]), "r"(a[3]), "r"(b[0]), "r"(b[1]));
}

#define LDSM_X4(R0,R1,R2,R3,ADDR) \
    asm volatile("ldmatrix.sync.aligned.m8n8.x4.shared.b16 {%0,%1,%2,%3}, [%4];" \
        : "=r"(R0), "=r"(R1), "=r"(R2), "=r"(R3) : "r"(ADDR))
#define LDSM_X4T(R0,R1,R2,R3,ADDR) \
    asm volatile("ldmatrix.sync.aligned.m8n8.x4.trans.shared.b16 {%0,%1,%2,%3}, [%4];" \
        : "=r"(R0), "=r"(R1), "=r"(R2), "=r"(R3) : "r"(ADDR))

#define CP_ASYNC16(dst_u32, src) \
    asm volatile("cp.async.cg.shared.global [%0], [%1], 16;" :: "r"(dst_u32), "l"(src))
#define CP_COMMIT() asm volatile("cp.async.commit_group;")
#define CP_WAIT(n)  asm volatile("cp.async.wait_group %0;" :: "n"(n))

// =============================================================================
// fp32 -> fp16 elementwise convert
// =============================================================================
__global__ __launch_bounds__(256) void f2h_kernel(const float* __restrict__ in,
                                                  __half* __restrict__ out, int n4)
{
    int i = blockIdx.x * blockDim.x + threadIdx.x;
    if (i >= n4) return;
    float4 v = ((const float4*)in)[i];
    ((uint2*)out)[i] = make_uint2(packh2(v.x, v.y), packh2(v.z, v.w));
}

#define GS2 72   // smem row stride in halves for BK=64 tiles (64 + 8 pad)

// =============================================================================
// QKV GEMM with fused bias + per-head LayerNorm epilogue. BK=64, 3-stage.
// Warps 4x2, warp tile 32x64 (one head per warp in N).
// =============================================================================
__global__ __launch_bounds__(256, 2) void gemm_qkv_ln(
    const __half* __restrict__ A, const __half* __restrict__ W,
    const float* __restrict__ bias,
    const float* __restrict__ qw, const float* __restrict__ qb,
    const float* __restrict__ kw, const float* __restrict__ kb,
    __half* __restrict__ Qo, __half* __restrict__ Ko, __half* __restrict__ Vo)
{
    extern __shared__ __half sg[];
    __half* As = sg;                   // [3][128][GS2]
    __half* Bs = sg + 3 * 128 * GS2;   // [3][128][GS2]

    const int K = C_;
    const int tid  = threadIdx.x;
    const int warp = tid >> 5, lane = tid & 31;
    const int mw   = warp >> 1, nw = warp & 1;      // 4 x 2 warp grid
    const int g    = lane >> 2, tg = lane & 3;
    const int bm   = blockIdx.y * 128, bn = blockIdx.x * 128;

    const int aR = (lane & 7) + ((lane >> 3) & 1) * 8;
    const int aC = (lane >> 4) * 8;
    const int bR = (lane & 7) + (lane >> 4) * 8;
    const int bC = ((lane >> 3) & 1) * 8;

    const int lrow = tid >> 3;            // 0..31
    const int lc8  = (tid & 7) * 8;       // 0..56

    const __half* Ap = A + (size_t)bm * K;
    const __half* Wp = W + (size_t)bn * K;

    const int T = K / 64;                 // 16 iterations

    auto issue = [&](int it) {
        const int st = it % 3;
        __half* as = As + st * 128 * GS2;
        __half* bs = Bs + st * 128 * GS2;
        #pragma unroll
        for (int j = 0; j < 4; j++) {
            const int row = lrow + 32 * j;
            CP_ASYNC16(saddr(&as[row * GS2 + lc8]), Ap + (size_t)row * K + it * 64 + lc8);
            CP_ASYNC16(saddr(&bs[row * GS2 + lc8]), Wp + (size_t)row * K + it * 64 + lc8);
        }
        CP_COMMIT();
    };

    float acc[2][8][4];
    #pragma unroll
    for (int i = 0; i < 2; i++)
        #pragma unroll
        for (int j = 0; j < 8; j++)
            #pragma unroll
            for (int e = 0; e < 4; e++) acc[i][j][e] = 0.f;

    issue(0);
    issue(1);

    for (int it = 0; it < T; it++) {
        if (it < T - 1) { CP_WAIT(1); } else { CP_WAIT(0); }
        __syncthreads();
        if (it + 2 < T) issue(it + 2);

        const int st = it % 3;
        __half* as = As + st * 128 * GS2;
        __half* bs = Bs + st * 128 * GS2;

        #pragma unroll
        for (int ks = 0; ks < 4; ks++) {
            const int kk = ks * 16;
            uint32_t a[2][4], b[8][2];
            #pragma unroll
            for (int mt = 0; mt < 2; mt++)
                LDSM_X4(a[mt][0], a[mt][1], a[mt][2], a[mt][3],
                        saddr(&as[(mw * 32 + mt * 16 + aR) * GS2 + kk + aC]));
            #pragma unroll
            for (int np = 0; np < 4; np++) {
                uint32_t r0, r1, r2, r3;
                LDSM_X4(r0, r1, r2, r3,
                        saddr(&bs[(nw * 64 + np * 16 + bR) * GS2 + kk + bC]));
                b[2*np][0] = r0; b[2*np][1] = r1;
                b[2*np+1][0] = r2; b[2*np+1][1] = r3;
            }
            #pragma unroll
            for (int mt = 0; mt < 2; mt++)
                #pragma unroll
                for (int nt = 0; nt < 8; nt++)
                    mma16(acc[mt][nt], a[mt], b[nt]);
        }
    }

    const int cn0 = bn + nw * 64;
    const int sec = cn0 >> 10;             // 0=q, 1=k, 2=v
    const int h   = (cn0 >> 6) & 15;

    float bz[16];
    #pragma unroll
    for (int nt = 0; nt < 8; nt++) {
        bz[2*nt]   = bias[cn0 + nt*8 + 2*tg];
        bz[2*nt+1] = bias[cn0 + nt*8 + 2*tg + 1];
    }
    float lnw[16], lnb[16];
    if (sec < 2) {
        const float* ws = (sec == 0) ? qw : kw;
        const float* bs2 = (sec == 0) ? qb : kb;
        #pragma unroll
        for (int nt = 0; nt < 8; nt++) {
            lnw[2*nt]   = ws[nt*8 + 2*tg];
            lnw[2*nt+1] = ws[nt*8 + 2*tg + 1];
            lnb[2*nt]   = bs2[nt*8 + 2*tg];
            lnb[2*nt+1] = bs2[nt*8 + 2*tg + 1];
        }
    }
    __half* dst = (sec == 0) ? Qo : (sec == 1) ? Ko : Vo;
    const float osc = (sec == 0) ? 0.125f * 1.44269504f : 1.0f;
    const float inv64 = 1.f / 64.f;

    #pragma unroll
    for (int mt = 0; mt < 2; mt++) {
        #pragma unroll
        for (int hh = 0; hh < 2; hh++) {
            const int grow = bm + mw * 32 + mt * 16 + hh * 8 + g;
            float v[16];
            float s = 0.f, ss = 0.f;
            #pragma unroll
            for (int nt = 0; nt < 8; nt++) {
                v[2*nt]   = acc[mt][nt][2*hh]     + bz[2*nt];
                v[2*nt+1] = acc[mt][nt][2*hh + 1] + bz[2*nt+1];
                s  += v[2*nt] + v[2*nt+1];
                ss += v[2*nt]*v[2*nt] + v[2*nt+1]*v[2*nt+1];
            }
            uint32_t outv[8];
            if (sec < 2) {
                s  += __shfl_xor_sync(0xffffffffu, s, 1);
                s  += __shfl_xor_sync(0xffffffffu, s, 2);
                ss += __shfl_xor_sync(0xffffffffu, ss, 1);
                ss += __shfl_xor_sync(0xffffffffu, ss, 2);
                const float mu = s * inv64;
                const float var = fmaxf(ss * inv64 - mu * mu, 0.f);
                const float rstd = rsqrtf(var + 1e-5f);
                #pragma unroll
                for (int nt = 0; nt < 8; nt++) {
                    float o0 = ((v[2*nt]   - mu) * rstd * lnw[2*nt]   + lnb[2*nt])   * osc;
                    float o1 = ((v[2*nt+1] - mu) * rstd * lnw[2*nt+1] + lnb[2*nt+1]) * osc;
                    outv[nt] = packh2(o0, o1);
                }
            } else {
                #pragma unroll
                for (int nt = 0; nt < 8; nt++)
                    outv[nt] = packh2(v[2*nt], v[2*nt+1]);
            }
            const int bb = grow >> 12, n = grow & (N_ - 1);
            __half* op = dst + ((size_t)((bb * H_ + h) * N_) + n) * D_ + 2 * tg;
            #pragma unroll
            for (int nt = 0; nt < 8; nt++)
                *(uint32_t*)(op + nt * 8) = outv[nt];
        }
    }
}

// =============================================================================
// fp16 GEMM for the output projection. BK=64, 3-stage, 2x4 warps (64x32 tile).
// =============================================================================
__global__ __launch_bounds__(256, 2) void gemm_h16(
    const __half* __restrict__ A, const __half* __restrict__ W,
    const float* __restrict__ bias, float* __restrict__ Cmat,
    int M, int Nout, int K)
{
    extern __shared__ __half sg[];
    __half* As = sg;
    __half* Bs = sg + 3 * 128 * GS2;

    const int tid  = threadIdx.x;
    const int warp = tid >> 5, lane = tid & 31;
    const int mw   = warp >> 2, nw = warp & 3;
    const int g    = lane >> 2, tg = lane & 3;
    const int bm   = blockIdx.y * 128, bn = blockIdx.x * 128;

    const int aR = (lane & 7) + ((lane >> 3) & 1) * 8;
    const int aC = (lane >> 4) * 8;
    const int bR = (lane & 7) + (lane >> 4) * 8;
    const int bC = ((lane >> 3) & 1) * 8;

    const int lrow = tid >> 3;
    const int lc8  = (tid & 7) * 8;

    const __half* Ap = A + (size_t)bm * K;
    const __half* Wp = W + (size_t)bn * K;

    const int T = K / 64;

    auto issue = [&](int it) {
        const int st = it % 3;
        __half* as = As + st * 128 * GS2;
        __half* bs = Bs + st * 128 * GS2;
        #pragma unroll
        for (int j = 0; j < 4; j++) {
            const int row = lrow + 32 * j;
            CP_ASYNC16(saddr(&as[row * GS2 + lc8]), Ap + (size_t)row * K + it * 64 + lc8);
            CP_ASYNC16(saddr(&bs[row * GS2 + lc8]), Wp + (size_t)row * K + it * 64 + lc8);
        }
        CP_COMMIT();
    };

    float acc[4][4][4];
    #pragma unroll
    for (int i = 0; i < 4; i++)
        #pragma unroll
        for (int j = 0; j < 4; j++)
            #pragma unroll
            for (int e = 0; e < 4; e++) acc[i][j][e] = 0.f;

    issue(0);
    issue(1);

    for (int it = 0; it < T; it++) {
        if (it < T - 1) { CP_WAIT(1); } else { CP_WAIT(0); }
        __syncthreads();
        if (it + 2 < T) issue(it + 2);

        const int st = it % 3;
        __half* as = As + st * 128 * GS2;
        __half* bs = Bs + st * 128 * GS2;

        #pragma unroll
        for (int ks = 0; ks < 4; ks++) {
            const int kk = ks * 16;
            uint32_t a[4][4], b[4][2];
            #pragma unroll
            for (int mt = 0; mt < 4; mt++)
                LDSM_X4(a[mt][0], a[mt][1], a[mt][2], a[mt][3],
                        saddr(&as[(mw * 64 + mt * 16 + aR) * GS2 + kk + aC]));
            #pragma unroll
            for (int np = 0; np < 2; np++) {
                uint32_t r0, r1, r2, r3;
                LDSM_X4(r0, r1, r2, r3,
                        saddr(&bs[(nw * 32 + np * 16 + bR) * GS2 + kk + bC]));
                b[2*np][0] = r0; b[2*np][1] = r1;
                b[2*np+1][0] = r2; b[2*np+1][1] = r3;
            }
            #pragma unroll
            for (int mt = 0; mt < 4; mt++)
                #pragma unroll
                for (int nt = 0; nt < 4; nt++)
                    mma16(acc[mt][nt], a[mt], b[nt]);
        }
    }

    #pragma unroll
    for (int mt = 0; mt < 4; mt++) {
        const int row0 = bm + mw * 64 + mt * 16 + g;
        #pragma unroll
        for (int nt = 0; nt < 4; nt++) {
            const int col = bn + nw * 32 + nt * 8 + 2 * tg;
            const float b0 = bias[col], b1 = bias[col + 1];
            *(float2*)(Cmat + (size_t)row0 * Nout + col) =
                make_float2(acc[mt][nt][0] + b0, acc[mt][nt][1] + b1);
            *(float2*)(Cmat + (size_t)(row0 + 8) * Nout + col) =
                make_float2(acc[mt][nt][2] + b0, acc[mt][nt][3] + b1);
        }
    }
}

// =============================================================================
// Flash attention: 128 q-rows/CTA, 256 threads, 8 warps x 16 rows.
// 4-stage K/V buffer processed in TILE PAIRS: one CP_WAIT + one __syncthreads
// per 2 tiles. No-max softmax (ex2.f16x2), l via ones-MMA. 2 CTAs/SM.
// =============================================================================
#define AST2 72

__global__ __launch_bounds__(256, 2) void attn_h16(
    const __half* __restrict__ Q, const __half* __restrict__ Kg,
    const __half* __restrict__ Vg, __half* __restrict__ AO)
{
    extern __shared__ __half sh[];
    __half* Qs = sh;                      // [128][AST2]
    __half* Ks = Qs + 128 * AST2;         // [4][64][AST2]
    __half* Vs = Ks + 4 * 64 * AST2;      // [4][64][AST2]

    const int tid  = threadIdx.x;
    const int warp = tid >> 5, lane = tid & 31;
    const int g    = lane >> 2, tg = lane & 3;
    const int bh   = blockIdx.y;
    const int q0   = blockIdx.x * 128;
    const int mrow = warp * 16;

    const int aR = (lane & 7) + ((lane >> 3) & 1) * 8;
    const int aC = (lane >> 4) * 8;
    const int bR = (lane & 7) + (lane >> 4) * 8;
    const int bC = ((lane >> 3) & 1) * 8;

    const __half* Qb = Q  + ((size_t)bh * N_ + q0) * D_;
    const __half* Kb = Kg + (size_t)bh * N_ * D_;
    const __half* Vb = Vg + (size_t)bh * N_ * D_;

    #pragma unroll
    for (int j = 0; j < 4; j++) {
        const int id  = tid + 256 * j;
        const int row = id >> 3;
        const int c8  = (id & 7) * 8;
        *(uint4*)&Qs[row * AST2 + c8] = *(const uint4*)(Qb + (size_t)row * D_ + c8);
    }

    const int lrow = tid >> 2;
    const int lc8  = (tid & 3) * 8;

    auto issueKV = [&](int t) {
        const int st = t & 3;
        const __half* kp = Kb + (size_t)(t * 64 + lrow) * D_ + lc8;
        const __half* vp = Vb + (size_t)(t * 64 + lrow) * D_ + lc8;
        __half* ks = &Ks[(st * 64 + lrow) * AST2 + lc8];
        __half* vs = &Vs[(st * 64 + lrow) * AST2 + lc8];
        CP_ASYNC16(saddr(ks),      kp);
        CP_ASYNC16(saddr(ks + 32), kp + 32);
        CP_ASYNC16(saddr(vs),      vp);
        CP_ASYNC16(saddr(vs + 32), vp + 32);
        CP_COMMIT();
    };

    // prime pair 0 (tiles 0,1)
    issueKV(0);
    issueKV(1);
    __syncthreads();   // Q stores visible

    uint32_t qf[4][4];
    #pragma unroll
    for (int ks = 0; ks < 4; ks++)
        LDSM_X4(qf[ks][0], qf[ks][1], qf[ks][2], qf[ks][3],
                saddr(&Qs[(mrow + aR) * AST2 + ks * 16 + aC]));

    float o[8][4];
    #pragma unroll
    for (int nt = 0; nt < 8; nt++)
        #pragma unroll
        for (int e = 0; e < 4; e++) o[nt][e] = 0.f;
    float lacc[4] = { 0.f, 0.f, 0.f, 0.f };
    const uint32_t bones[2] = { 0x3C003C00u, 0x3C003C00u };

    const int P = N_ / 128;   // 32 pairs of key tiles
    for (int p = 0; p < P; p++) {
        CP_WAIT(0);           // pair p arrived (only outstanding group set)
        __syncthreads();      // visible to all; all warps done reading pair p-1
        if (p + 1 < P) {      // prefetch pair p+1 into the other stage-half
            issueKV(2 * p + 2);
            issueKV(2 * p + 3);
        }

        #pragma unroll
        for (int half = 0; half < 2; half++) {
            const int t  = 2 * p + half;
            const int st = t & 3;
            const __half* Kc = Ks + st * 64 * AST2;
            const __half* Vc = Vs + st * 64 * AST2;

            // ---- S = Q @ K^T ----
            float sacc[8][4];
            #pragma unroll
            for (int nt = 0; nt < 8; nt++)
                #pragma unroll
                for (int e = 0; e < 4; e++) sacc[nt][e] = 0.f;

            #pragma unroll
            for (int ks = 0; ks < 4; ks++) {
                const int kk = ks * 16;
                #pragma unroll
                for (int np = 0; np < 4; np++) {
                    uint32_t r0, r1, r2, r3;
                    LDSM_X4(r0, r1, r2, r3,
                            saddr(&Kc[(np * 16 + bR) * AST2 + kk + bC]));
                    uint32_t b0[2] = { r0, r1 }, b1[2] = { r2, r3 };
                    mma16(sacc[2*np],     qf[ks], b0);
                    mma16(sacc[2*np + 1], qf[ks], b1);
                }
            }

            // ---- p = exp2(s) in f16x2 ----
            uint32_t ph[8][2];
            #pragma unroll
            for (int nt = 0; nt < 8; nt++) {
                uint32_t lo = packh2(sacc[nt][0], sacc[nt][1]);
                uint32_t hi = packh2(sacc[nt][2], sacc[nt][3]);
                asm("ex2.approx.f16x2 %0, %1;" : "=r"(ph[nt][0]) : "r"(lo));
                asm("ex2.approx.f16x2 %0, %1;" : "=r"(ph[nt][1]) : "r"(hi));
            }

            // ---- O += P @ V ; l += P @ ones ----
            #pragma unroll
            for (int ks = 0; ks < 4; ks++) {
                const int kk = ks * 16;
                uint32_t a[4] = { ph[2*ks][0], ph[2*ks][1], ph[2*ks+1][0], ph[2*ks+1][1] };
                mma16(lacc, a, bones);
                #pragma unroll
                for (int dp = 0; dp < 4; dp++) {
                    uint32_t r0, r1, r2, r3;
                    LDSM_X4T(r0, r1, r2, r3,
                             saddr(&Vc[(kk + aR) * AST2 + dp * 16 + aC]));
                    uint32_t b0[2] = { r0, r1 }, b1[2] = { r2, r3 };
                    mma16(o[2*dp],     a, b0);
                    mma16(o[2*dp + 1], a, b1);
                }
            }
        }
    }

    // ---- epilogue ----
    const float inv0 = 1.f / lacc[0], inv1 = 1.f / lacc[2];

    const int b = bh >> 4, h = bh & 15;
    __half* op = AO + ((size_t)(b * N_ + q0 + mrow + g)) * C_ + h * D_;
    #pragma unroll
    for (int nt = 0; nt < 8; nt++) {
        const int col = nt * 8 + 2 * tg;
        *(__half2*)(op + col) = __floats2half2_rn(o[nt][0] * inv0, o[nt][1] * inv0);
        *(__half2*)(op + (size_t)8 * C_ + col) =
            __floats2half2_rn(o[nt][2] * inv1, o[nt][3] * inv1);
    }
}

// =============================================================================
extern "C" void kernel_launch(void* const* d_in, const int* in_sizes, int n_in,
                              void* d_out, int out_size)
{
    const float* x      = (const float*)d_in[0];
    const float* qkv_w  = (const float*)d_in[1];
    const float* qkv_b  = (const float*)d_in[2];
    const float* qnw    = (const float*)d_in[3];
    const float* qnb    = (const float*)d_in[4];
    const float* knw    = (const float*)d_in[5];
    const float* knb    = (const float*)d_in[6];
    const float* proj_w = (const float*)d_in[7];
    const float* proj_b = (const float*)d_in[8];
    float* out = (float*)d_out;

    __half *xh, *wqkv, *wproj, *q, *k, *v, *ao;
    cudaGetSymbolAddress((void**)&xh,    g_xh);
    cudaGetSymbolAddress((void**)&wqkv,  g_wqkv_h);
    cudaGetSymbolAddress((void**)&wproj, g_wproj_h);
    cudaGetSymbolAddress((void**)&q,     g_q);
    cudaGetSymbolAddress((void**)&k,     g_k);
    cudaGetSymbolAddress((void**)&v,     g_v);
    cudaGetSymbolAddress((void**)&ao,    g_ao);

    const int gemm_smem = 2 * 3 * 128 * GS2 * (int)sizeof(__half);     // 110592
    const int attn_smem = (128 + 8 * 64) * AST2 * (int)sizeof(__half); // 92160
    cudaFuncSetAttribute(gemm_h16, cudaFuncAttributeMaxDynamicSharedMemorySize, gemm_smem);
    cudaFuncSetAttribute(gemm_qkv_ln, cudaFuncAttributeMaxDynamicSharedMemorySize, gemm_smem);
    cudaFuncSetAttribute(attn_h16, cudaFuncAttributeMaxDynamicSharedMemorySize, attn_smem);

    // 0) fp16 preconversion
    {
        int n4x = (B_ * N_ * C_) / 4;
        f2h_kernel<<<(n4x + 255) / 256, 256>>>(x, xh, n4x);
        int n4w = (3 * C_ * C_) / 4;
        f2h_kernel<<<(n4w + 255) / 256, 256>>>(qkv_w, wqkv, n4w);
        int n4p = (C_ * C_) / 4;
        f2h_kernel<<<(n4p + 255) / 256, 256>>>(proj_w, wproj, n4p);
    }
    // 1) QKV projection + fused bias/LN/split
    {
        dim3 grid(3 * C_ / 128, (B_ * N_) / 128);
        gemm_qkv_ln<<<grid, 256, gemm_smem>>>(xh, wqkv, qkv_b,
                                              qnw, qnb, knw, knb, q, k, v);
    }
    // 2) attention (pair-processed key tiles)
    {
        dim3 grid(N_ / 128, BH_);
        attn_h16<<<grid, 256, attn_smem>>>(q, k, v, ao);
    }
    // 3) output projection -> d_out
    {
        dim3 grid(C_ / 128, (B_ * N_) / 128);
        gemm_h16<<<grid, 256, gemm_smem>>>(ao, wproj, proj_b, out, B_ * N_, C_, C_);
    }
}

// round 13
// speedup vs baseline: 1.6581x; 1.0100x over previous
#include <cuda_runtime.h>
#include <cuda_fp16.h>
#include <math.h>
#include <stdint.h>
#include <stddef.h>

#define B_  2
#define N_  4096
#define C_  1024
#define H_  16
#define D_  64
#define BH_ (B_*H_)

// ---------------- scratch (device globals; no allocs allowed) ----------------
__device__ __half g_xh    [(size_t)B_*N_*C_];     // x in fp16
__device__ __half g_wqkv_h[(size_t)3*C_*C_];      // qkv_w fp16
__device__ __half g_wproj_h[(size_t)C_*C_];       // proj_w fp16
__device__ __half g_q [(size_t)BH_*N_*D_];        // LN'd, pre-scaled by 0.125*log2e
__device__ __half g_k [(size_t)BH_*N_*D_];
__device__ __half g_v [(size_t)BH_*N_*D_];
__device__ __half g_ao[(size_t)B_*N_*C_];         // [B,N,C] attention out fp16

// ---------------- helpers ----------------
__device__ __forceinline__ uint32_t packh2(float x, float y) {
    __half2 h = __floats2half2_rn(x, y);
    return *(uint32_t*)&h;
}
__device__ __forceinline__ uint32_t saddr(const void* p) {
    return (uint32_t)__cvta_generic_to_shared(p);
}

__device__ __forceinline__ void mma16(float* c, const uint32_t* a, const uint32_t* b) {
    asm volatile(
        "mma.sync.aligned.m16n8k16.row.col.f32.f16.f16.f32 "
        "{%0,%1,%2,%3}, {%4,%5,%6,%7}, {%8,%9}, {%0,%1,%2,%3};"
        : "+f"(c[0]), "+f"(c[1]), "+f"(c[2]), "+f"(c[3])
        : "r"(a[0]), "r"(a[1]), "r"(a[2]), "r"(a[3]), "r"(b[0]), "r"(b[1]));
}

// fp16-accumulator variant: C/D = 2x f16x2 regs (row g | row g+8, cols 2tg,2tg+1)
__device__ __forceinline__ void mma16h(uint32_t* c, const uint32_t* a, const uint32_t* b) {
    asm volatile(
        "mma.sync.aligned.m16n8k16.row.col.f16.f16.f16.f16 "
        "{%0,%1}, {%2,%3,%4,%5}, {%6,%7}, {%0,%1};"
        : "+r"(c[0]), "+r"(c[1])
        : "r"(a[0]), "r"(a[1]), "r"(a[2]), "r"(a[3]), "r"(b[0]), "r"(b[1]));
}

#define LDSM_X4(R0,R1,R2,R3,ADDR) \
    asm volatile("ldmatrix.sync.aligned.m8n8.x4.shared.b16 {%0,%1,%2,%3}, [%4];" \
        : "=r"(R0), "=r"(R1), "=r"(R2), "=r"(R3) : "r"(ADDR))
#define LDSM_X4T(R0,R1,R2,R3,ADDR) \
    asm volatile("ldmatrix.sync.aligned.m8n8.x4.trans.shared.b16 {%0,%1,%2,%3}, [%4];" \
        : "=r"(R0), "=r"(R1), "=r"(R2), "=r"(R3) : "r"(ADDR))

#define CP_ASYNC16(dst_u32, src) \
    asm volatile("cp.async.cg.shared.global [%0], [%1], 16;" :: "r"(dst_u32), "l"(src))
#define CP_COMMIT() asm volatile("cp.async.commit_group;")
#define CP_WAIT(n)  asm volatile("cp.async.wait_group %0;" :: "n"(n))

// =============================================================================
// fp32 -> fp16 elementwise convert
// =============================================================================
__global__ __launch_bounds__(256) void f2h_kernel(const float* __restrict__ in,
                                                  __half* __restrict__ out, int n4)
{
    int i = blockIdx.x * blockDim.x + threadIdx.x;
    if (i >= n4) return;
    float4 v = ((const float4*)in)[i];
    ((uint2*)out)[i] = make_uint2(packh2(v.x, v.y), packh2(v.z, v.w));
}

#define GS2 72   // smem row stride in halves for BK=64 tiles (64 + 8 pad)

// =============================================================================
// QKV GEMM with fused bias + per-head LayerNorm epilogue. BK=64, 3-stage.
// =============================================================================
__global__ __launch_bounds__(256, 2) void gemm_qkv_ln(
    const __half* __restrict__ A, const __half* __restrict__ W,
    const float* __restrict__ bias,
    const float* __restrict__ qw, const float* __restrict__ qb,
    const float* __restrict__ kw, const float* __restrict__ kb,
    __half* __restrict__ Qo, __half* __restrict__ Ko, __half* __restrict__ Vo)
{
    extern __shared__ __half sg[];
    __half* As = sg;                   // [3][128][GS2]
    __half* Bs = sg + 3 * 128 * GS2;   // [3][128][GS2]

    const int K = C_;
    const int tid  = threadIdx.x;
    const int warp = tid >> 5, lane = tid & 31;
    const int mw   = warp >> 1, nw = warp & 1;      // 4 x 2 warp grid
    const int g    = lane >> 2, tg = lane & 3;
    const int bm   = blockIdx.y * 128, bn = blockIdx.x * 128;

    const int aR = (lane & 7) + ((lane >> 3) & 1) * 8;
    const int aC = (lane >> 4) * 8;
    const int bR = (lane & 7) + (lane >> 4) * 8;
    const int bC = ((lane >> 3) & 1) * 8;

    const int lrow = tid >> 3;            // 0..31
    const int lc8  = (tid & 7) * 8;       // 0..56

    const __half* Ap = A + (size_t)bm * K;
    const __half* Wp = W + (size_t)bn * K;

    const int T = K / 64;                 // 16 iterations

    auto issue = [&](int it) {
        const int st = it % 3;
        __half* as = As + st * 128 * GS2;
        __half* bs = Bs + st * 128 * GS2;
        #pragma unroll
        for (int j = 0; j < 4; j++) {
            const int row = lrow + 32 * j;
            CP_ASYNC16(saddr(&as[row * GS2 + lc8]), Ap + (size_t)row * K + it * 64 + lc8);
            CP_ASYNC16(saddr(&bs[row * GS2 + lc8]), Wp + (size_t)row * K + it * 64 + lc8);
        }
        CP_COMMIT();
    };

    float acc[2][8][4];
    #pragma unroll
    for (int i = 0; i < 2; i++)
        #pragma unroll
        for (int j = 0; j < 8; j++)
            #pragma unroll
            for (int e = 0; e < 4; e++) acc[i][j][e] = 0.f;

    issue(0);
    issue(1);

    for (int it = 0; it < T; it++) {
        if (it < T - 1) { CP_WAIT(1); } else { CP_WAIT(0); }
        __syncthreads();
        if (it + 2 < T) issue(it + 2);

        const int st = it % 3;
        __half* as = As + st * 128 * GS2;
        __half* bs = Bs + st * 128 * GS2;

        #pragma unroll
        for (int ks = 0; ks < 4; ks++) {
            const int kk = ks * 16;
            uint32_t a[2][4], b[8][2];
            #pragma unroll
            for (int mt = 0; mt < 2; mt++)
                LDSM_X4(a[mt][0], a[mt][1], a[mt][2], a[mt][3],
                        saddr(&as[(mw * 32 + mt * 16 + aR) * GS2 + kk + aC]));
            #pragma unroll
            for (int np = 0; np < 4; np++) {
                uint32_t r0, r1, r2, r3;
                LDSM_X4(r0, r1, r2, r3,
                        saddr(&bs[(nw * 64 + np * 16 + bR) * GS2 + kk + bC]));
                b[2*np][0] = r0; b[2*np][1] = r1;
                b[2*np+1][0] = r2; b[2*np+1][1] = r3;
            }
            #pragma unroll
            for (int mt = 0; mt < 2; mt++)
                #pragma unroll
                for (int nt = 0; nt < 8; nt++)
                    mma16(acc[mt][nt], a[mt], b[nt]);
        }
    }

    const int cn0 = bn + nw * 64;
    const int sec = cn0 >> 10;             // 0=q, 1=k, 2=v
    const int h   = (cn0 >> 6) & 15;

    float bz[16];
    #pragma unroll
    for (int nt = 0; nt < 8; nt++) {
        bz[2*nt]   = bias[cn0 + nt*8 + 2*tg];
        bz[2*nt+1] = bias[cn0 + nt*8 + 2*tg + 1];
    }
    float lnw[16], lnb[16];
    if (sec < 2) {
        const float* ws = (sec == 0) ? qw : kw;
        const float* bs2 = (sec == 0) ? qb : kb;
        #pragma unroll
        for (int nt = 0; nt < 8; nt++) {
            lnw[2*nt]   = ws[nt*8 + 2*tg];
            lnw[2*nt+1] = ws[nt*8 + 2*tg + 1];
            lnb[2*nt]   = bs2[nt*8 + 2*tg];
            lnb[2*nt+1] = bs2[nt*8 + 2*tg + 1];
        }
    }
    __half* dst = (sec == 0) ? Qo : (sec == 1) ? Ko : Vo;
    const float osc = (sec == 0) ? 0.125f * 1.44269504f : 1.0f;
    const float inv64 = 1.f / 64.f;

    #pragma unroll
    for (int mt = 0; mt < 2; mt++) {
        #pragma unroll
        for (int hh = 0; hh < 2; hh++) {
            const int grow = bm + mw * 32 + mt * 16 + hh * 8 + g;
            float v[16];
            float s = 0.f, ss = 0.f;
            #pragma unroll
            for (int nt = 0; nt < 8; nt++) {
                v[2*nt]   = acc[mt][nt][2*hh]     + bz[2*nt];
                v[2*nt+1] = acc[mt][nt][2*hh + 1] + bz[2*nt+1];
                s  += v[2*nt] + v[2*nt+1];
                ss += v[2*nt]*v[2*nt] + v[2*nt+1]*v[2*nt+1];
            }
            uint32_t outv[8];
            if (sec < 2) {
                s  += __shfl_xor_sync(0xffffffffu, s, 1);
                s  += __shfl_xor_sync(0xffffffffu, s, 2);
                ss += __shfl_xor_sync(0xffffffffu, ss, 1);
                ss += __shfl_xor_sync(0xffffffffu, ss, 2);
                const float mu = s * inv64;
                const float var = fmaxf(ss * inv64 - mu * mu, 0.f);
                const float rstd = rsqrtf(var + 1e-5f);
                #pragma unroll
                for (int nt = 0; nt < 8; nt++) {
                    float o0 = ((v[2*nt]   - mu) * rstd * lnw[2*nt]   + lnb[2*nt])   * osc;
                    float o1 = ((v[2*nt+1] - mu) * rstd * lnw[2*nt+1] + lnb[2*nt+1]) * osc;
                    outv[nt] = packh2(o0, o1);
                }
            } else {
                #pragma unroll
                for (int nt = 0; nt < 8; nt++)
                    outv[nt] = packh2(v[2*nt], v[2*nt+1]);
            }
            const int bb = grow >> 12, n = grow & (N_ - 1);
            __half* op = dst + ((size_t)((bb * H_ + h) * N_) + n) * D_ + 2 * tg;
            #pragma unroll
            for (int nt = 0; nt < 8; nt++)
                *(uint32_t*)(op + nt * 8) = outv[nt];
        }
    }
}

// =============================================================================
// fp16 GEMM for the output projection. BK=64, 3-stage, 2x4 warps.
// =============================================================================
__global__ __launch_bounds__(256, 2) void gemm_h16(
    const __half* __restrict__ A, const __half* __restrict__ W,
    const float* __restrict__ bias, float* __restrict__ Cmat,
    int M, int Nout, int K)
{
    extern __shared__ __half sg[];
    __half* As = sg;
    __half* Bs = sg + 3 * 128 * GS2;

    const int tid  = threadIdx.x;
    const int warp = tid >> 5, lane = tid & 31;
    const int mw   = warp >> 2, nw = warp & 3;
    const int g    = lane >> 2, tg = lane & 3;
    const int bm   = blockIdx.y * 128, bn = blockIdx.x * 128;

    const int aR = (lane & 7) + ((lane >> 3) & 1) * 8;
    const int aC = (lane >> 4) * 8;
    const int bR = (lane & 7) + (lane >> 4) * 8;
    const int bC = ((lane >> 3) & 1) * 8;

    const int lrow = tid >> 3;
    const int lc8  = (tid & 7) * 8;

    const __half* Ap = A + (size_t)bm * K;
    const __half* Wp = W + (size_t)bn * K;

    const int T = K / 64;

    auto issue = [&](int it) {
        const int st = it % 3;
        __half* as = As + st * 128 * GS2;
        __half* bs = Bs + st * 128 * GS2;
        #pragma unroll
        for (int j = 0; j < 4; j++) {
            const int row = lrow + 32 * j;
            CP_ASYNC16(saddr(&as[row * GS2 + lc8]), Ap + (size_t)row * K + it * 64 + lc8);
            CP_ASYNC16(saddr(&bs[row * GS2 + lc8]), Wp + (size_t)row * K + it * 64 + lc8);
        }
        CP_COMMIT();
    };

    float acc[4][4][4];
    #pragma unroll
    for (int i = 0; i < 4; i++)
        #pragma unroll
        for (int j = 0; j < 4; j++)
            #pragma unroll
            for (int e = 0; e < 4; e++) acc[i][j][e] = 0.f;

    issue(0);
    issue(1);

    for (int it = 0; it < T; it++) {
        if (it < T - 1) { CP_WAIT(1); } else { CP_WAIT(0); }
        __syncthreads();
        if (it + 2 < T) issue(it + 2);

        const int st = it % 3;
        __half* as = As + st * 128 * GS2;
        __half* bs = Bs + st * 128 * GS2;

        #pragma unroll
        for (int ks = 0; ks < 4; ks++) {
            const int kk = ks * 16;
            uint32_t a[4][4], b[4][2];
            #pragma unroll
            for (int mt = 0; mt < 4; mt++)
                LDSM_X4(a[mt][0], a[mt][1], a[mt][2], a[mt][3],
                        saddr(&as[(mw * 64 + mt * 16 + aR) * GS2 + kk + aC]));
            #pragma unroll
            for (int np = 0; np < 2; np++) {
                uint32_t r0, r1, r2, r3;
                LDSM_X4(r0, r1, r2, r3,
                        saddr(&bs[(nw * 32 + np * 16 + bR) * GS2 + kk + bC]));
                b[2*np][0] = r0; b[2*np][1] = r1;
                b[2*np+1][0] = r2; b[2*np+1][1] = r3;
            }
            #pragma unroll
            for (int mt = 0; mt < 4; mt++)
                #pragma unroll
                for (int nt = 0; nt < 4; nt++)
                    mma16(acc[mt][nt], a[mt], b[nt]);
        }
    }

    #pragma unroll
    for (int mt = 0; mt < 4; mt++) {
        const int row0 = bm + mw * 64 + mt * 16 + g;
        #pragma unroll
        for (int nt = 0; nt < 4; nt++) {
            const int col = bn + nw * 32 + nt * 8 + 2 * tg;
            const float b0 = bias[col], b1 = bias[col + 1];
            *(float2*)(Cmat + (size_t)row0 * Nout + col) =
                make_float2(acc[mt][nt][0] + b0, acc[mt][nt][1] + b1);
            *(float2*)(Cmat + (size_t)(row0 + 8) * Nout + col) =
                make_float2(acc[mt][nt][2] + b0, acc[mt][nt][3] + b1);
        }
    }
}

// =============================================================================
// Flash attention: 128 q-rows/CTA, 8 warps x 16 rows. S-MMA in fp16 acc
// (layout == PV A-frag layout: zero-conversion softmax). Pair-processed
// 4-stage K/V pipeline. l via ones-MMA (fp32). 2 CTAs/SM.
// =============================================================================
#define AST2 72

__global__ __launch_bounds__(256, 2) void attn_h16(
    const __half* __restrict__ Q, const __half* __restrict__ Kg,
    const __half* __restrict__ Vg, __half* __restrict__ AO)
{
    extern __shared__ __half sh[];
    __half* Qs = sh;                      // [128][AST2]
    __half* Ks = Qs + 128 * AST2;         // [4][64][AST2]
    __half* Vs = Ks + 4 * 64 * AST2;      // [4][64][AST2]

    const int tid  = threadIdx.x;
    const int warp = tid >> 5, lane = tid & 31;
    const int g    = lane >> 2, tg = lane & 3;
    const int bh   = blockIdx.y;
    const int q0   = blockIdx.x * 128;
    const int mrow = warp * 16;

    const int aR = (lane & 7) + ((lane >> 3) & 1) * 8;
    const int aC = (lane >> 4) * 8;
    const int bR = (lane & 7) + (lane >> 4) * 8;
    const int bC = ((lane >> 3) & 1) * 8;

    const __half* Qb = Q  + ((size_t)bh * N_ + q0) * D_;
    const __half* Kb = Kg + (size_t)bh * N_ * D_;
    const __half* Vb = Vg + (size_t)bh * N_ * D_;

    #pragma unroll
    for (int j = 0; j < 4; j++) {
        const int id  = tid + 256 * j;
        const int row = id >> 3;
        const int c8  = (id & 7) * 8;
        *(uint4*)&Qs[row * AST2 + c8] = *(const uint4*)(Qb + (size_t)row * D_ + c8);
    }

    const int lrow = tid >> 2;
    const int lc8  = (tid & 3) * 8;

    auto issueKV = [&](int t) {
        const int st = t & 3;
        const __half* kp = Kb + (size_t)(t * 64 + lrow) * D_ + lc8;
        const __half* vp = Vb + (size_t)(t * 64 + lrow) * D_ + lc8;
        __half* ks = &Ks[(st * 64 + lrow) * AST2 + lc8];
        __half* vs = &Vs[(st * 64 + lrow) * AST2 + lc8];
        CP_ASYNC16(saddr(ks),      kp);
        CP_ASYNC16(saddr(ks + 32), kp + 32);
        CP_ASYNC16(saddr(vs),      vp);
        CP_ASYNC16(saddr(vs + 32), vp + 32);
        CP_COMMIT();
    };

    // prime pair 0 (tiles 0,1)
    issueKV(0);
    issueKV(1);
    __syncthreads();   // Q stores visible

    uint32_t qf[4][4];
    #pragma unroll
    for (int ks = 0; ks < 4; ks++)
        LDSM_X4(qf[ks][0], qf[ks][1], qf[ks][2], qf[ks][3],
                saddr(&Qs[(mrow + aR) * AST2 + ks * 16 + aC]));

    float o[8][4];
    #pragma unroll
    for (int nt = 0; nt < 8; nt++)
        #pragma unroll
        for (int e = 0; e < 4; e++) o[nt][e] = 0.f;
    float lacc[4] = { 0.f, 0.f, 0.f, 0.f };
    const uint32_t bones[2] = { 0x3C003C00u, 0x3C003C00u };

    const int P = N_ / 128;   // 32 pairs of key tiles
    for (int p = 0; p < P; p++) {
        CP_WAIT(0);           // pair p arrived
        __syncthreads();
        if (p + 1 < P) {
            issueKV(2 * p + 2);
            issueKV(2 * p + 3);
        }

        #pragma unroll
        for (int half = 0; half < 2; half++) {
            const int t  = 2 * p + half;
            const int st = t & 3;
            const __half* Kc = Ks + st * 64 * AST2;
            const __half* Vc = Vs + st * 64 * AST2;

            // ---- S = Q @ K^T, fp16 accumulator ----
            uint32_t sh_acc[8][2];
            #pragma unroll
            for (int nt = 0; nt < 8; nt++) { sh_acc[nt][0] = 0u; sh_acc[nt][1] = 0u; }

            #pragma unroll
            for (int ks = 0; ks < 4; ks++) {
                const int kk = ks * 16;
                #pragma unroll
                for (int np = 0; np < 4; np++) {
                    uint32_t r0, r1, r2, r3;
                    LDSM_X4(r0, r1, r2, r3,
                            saddr(&Kc[(np * 16 + bR) * AST2 + kk + bC]));
                    uint32_t b0[2] = { r0, r1 }, b1[2] = { r2, r3 };
                    mma16h(sh_acc[2*np],     qf[ks], b0);
                    mma16h(sh_acc[2*np + 1], qf[ks], b1);
                }
            }

            // ---- p = exp2(s) in-place on f16x2 accumulators ----
            #pragma unroll
            for (int nt = 0; nt < 8; nt++) {
                asm("ex2.approx.f16x2 %0, %0;" : "+r"(sh_acc[nt][0]));
                asm("ex2.approx.f16x2 %0, %0;" : "+r"(sh_acc[nt][1]));
            }

            // ---- O += P @ V ; l += P @ ones (P frags = sh_acc, no conversion) ----
            #pragma unroll
            for (int ks = 0; ks < 4; ks++) {
                const int kk = ks * 16;
                uint32_t a[4] = { sh_acc[2*ks][0], sh_acc[2*ks][1],
                                  sh_acc[2*ks+1][0], sh_acc[2*ks+1][1] };
                mma16(lacc, a, bones);
                #pragma unroll
                for (int dp = 0; dp < 4; dp++) {
                    uint32_t r0, r1, r2, r3;
                    LDSM_X4T(r0, r1, r2, r3,
                             saddr(&Vc[(kk + aR) * AST2 + dp * 16 + aC]));
                    uint32_t b0[2] = { r0, r1 }, b1[2] = { r2, r3 };
                    mma16(o[2*dp],     a, b0);
                    mma16(o[2*dp + 1], a, b1);
                }
            }
        }
    }

    // ---- epilogue ----
    const float inv0 = 1.f / lacc[0], inv1 = 1.f / lacc[2];

    const int b = bh >> 4, h = bh & 15;
    __half* op = AO + ((size_t)(b * N_ + q0 + mrow + g)) * C_ + h * D_;
    #pragma unroll
    for (int nt = 0; nt < 8; nt++) {
        const int col = nt * 8 + 2 * tg;
        *(__half2*)(op + col) = __floats2half2_rn(o[nt][0] * inv0, o[nt][1] * inv0);
        *(__half2*)(op + (size_t)8 * C_ + col) =
            __floats2half2_rn(o[nt][2] * inv1, o[nt][3] * inv1);
    }
}

// =============================================================================
extern "C" void kernel_launch(void* const* d_in, const int* in_sizes, int n_in,
                              void* d_out, int out_size)
{
    const float* x      = (const float*)d_in[0];
    const float* qkv_w  = (const float*)d_in[1];
    const float* qkv_b  = (const float*)d_in[2];
    const float* qnw    = (const float*)d_in[3];
    const float* qnb    = (const float*)d_in[4];
    const float* knw    = (const float*)d_in[5];
    const float* knb    = (const float*)d_in[6];
    const float* proj_w = (const float*)d_in[7];
    const float* proj_b = (const float*)d_in[8];
    float* out = (float*)d_out;

    __half *xh, *wqkv, *wproj, *q, *k, *v, *ao;
    cudaGetSymbolAddress((void**)&xh,    g_xh);
    cudaGetSymbolAddress((void**)&wqkv,  g_wqkv_h);
    cudaGetSymbolAddress((void**)&wproj, g_wproj_h);
    cudaGetSymbolAddress((void**)&q,     g_q);
    cudaGetSymbolAddress((void**)&k,     g_k);
    cudaGetSymbolAddress((void**)&v,     g_v);
    cudaGetSymbolAddress((void**)&ao,    g_ao);

    const int gemm_smem = 2 * 3 * 128 * GS2 * (int)sizeof(__half);     // 110592
    const int attn_smem = (128 + 8 * 64) * AST2 * (int)sizeof(__half); // 92160
    cudaFuncSetAttribute(gemm_h16, cudaFuncAttributeMaxDynamicSharedMemorySize, gemm_smem);
    cudaFuncSetAttribute(gemm_qkv_ln, cudaFuncAttributeMaxDynamicSharedMemorySize, gemm_smem);
    cudaFuncSetAttribute(attn_h16, cudaFuncAttributeMaxDynamicSharedMemorySize, attn_smem);

    // 0) fp16 preconversion
    {
        int n4x = (B_ * N_ * C_) / 4;
        f2h_kernel<<<(n4x + 255) / 256, 256>>>(x, xh, n4x);
        int n4w = (3 * C_ * C_) / 4;
        f2h_kernel<<<(n4w + 255) / 256, 256>>>(qkv_w, wqkv, n4w);
        int n4p = (C_ * C_) / 4;
        f2h_kernel<<<(n4p + 255) / 256, 256>>>(proj_w, wproj, n4p);
    }
    // 1) QKV projection + fused bias/LN/split
    {
        dim3 grid(3 * C_ / 128, (B_ * N_) / 128);
        gemm_qkv_ln<<<grid, 256, gemm_smem>>>(xh, wqkv, qkv_b,
                                              qnw, qnb, knw, knb, q, k, v);
    }
    // 2) attention (fp16-acc S, zero-conversion softmax)
    {
        dim3 grid(N_ / 128, BH_);
        attn_h16<<<grid, 256, attn_smem>>>(q, k, v, ao);
    }
    // 3) output projection -> d_out
    {
        dim3 grid(C_ / 128, (B_ * N_) / 128);
        gemm_h16<<<grid, 256, gemm_smem>>>(ao, wproj, proj_b, out, B_ * N_, C_, C_);
    }
}

// round 15
// speedup vs baseline: 1.8271x; 1.1019x over previous
#include <cuda_runtime.h>
#include <cuda_fp16.h>
#include <math.h>
#include <stdint.h>
#include <stddef.h>

#define B_  2
#define N_  4096
#define C_  1024
#define H_  16
#define D_  64
#define BH_ (B_*H_)

// ---------------- scratch (device globals; no allocs allowed) ----------------
__device__ __half g_xh    [(size_t)B_*N_*C_];     // x in fp16
__device__ __half g_wqkv_h[(size_t)3*C_*C_];      // qkv_w fp16
__device__ __half g_wproj_h[(size_t)C_*C_];       // proj_w fp16
__device__ __half g_q [(size_t)BH_*N_*D_];        // LN'd, pre-scaled by 0.125*log2e
__device__ __half g_k [(size_t)BH_*N_*D_];
__device__ __half g_v [(size_t)BH_*N_*D_];
__device__ __half g_ao[(size_t)B_*N_*C_];         // [B,N,C] attention out fp16

// ---------------- helpers ----------------
__device__ __forceinline__ uint32_t packh2(float x, float y) {
    __half2 h = __floats2half2_rn(x, y);
    return *(uint32_t*)&h;
}
__device__ __forceinline__ uint32_t saddr(const void* p) {
    return (uint32_t)__cvta_generic_to_shared(p);
}

__device__ __forceinline__ void mma16(float* c, const uint32_t* a, const uint32_t* b) {
    asm volatile(
        "mma.sync.aligned.m16n8k16.row.col.f32.f16.f16.f32 "
        "{%0,%1,%2,%3}, {%4,%5,%6,%7}, {%8,%9}, {%0,%1,%2,%3};"
        : "+f"(c[0]), "+f"(c[1]), "+f"(c[2]), "+f"(c[3])
        : "r"(a[0]), "r"(a[1]), "r"(a[2]), "r"(a[3]), "r"(b[0]), "r"(b[1]));
}

// fp16-accumulator variant: C/D = 2x f16x2 regs (row g | row g+8, cols 2tg,2tg+1)
__device__ __forceinline__ void mma16h(uint32_t* c, const uint32_t* a, const uint32_t* b) {
    asm volatile(
        "mma.sync.aligned.m16n8k16.row.col.f16.f16.f16.f16 "
        "{%0,%1}, {%2,%3,%4,%5}, {%6,%7}, {%0,%1};"
        : "+r"(c[0]), "+r"(c[1])
        : "r"(a[0]), "r"(a[1]), "r"(a[2]), "r"(a[3]), "r"(b[0]), "r"(b[1]));
}

#define LDSM_X4(R0,R1,R2,R3,ADDR) \
    asm volatile("ldmatrix.sync.aligned.m8n8.x4.shared.b16 {%0,%1,%2,%3}, [%4];" \
        : "=r"(R0), "=r"(R1), "=r"(R2), "=r"(R3) : "r"(ADDR))
#define LDSM_X4T(R0,R1,R2,R3,ADDR) \
    asm volatile("ldmatrix.sync.aligned.m8n8.x4.trans.shared.b16 {%0,%1,%2,%3}, [%4];" \
        : "=r"(R0), "=r"(R1), "=r"(R2), "=r"(R3) : "r"(ADDR))

#define CP_ASYNC16(dst_u32, src) \
    asm volatile("cp.async.cg.shared.global [%0], [%1], 16;" :: "r"(dst_u32), "l"(src))
#define CP_COMMIT() asm volatile("cp.async.commit_group;")
#define CP_WAIT(n)  asm volatile("cp.async.wait_group %0;" :: "n"(n))

// =============================================================================
// fp32 -> fp16 elementwise convert
// =============================================================================
__global__ __launch_bounds__(256) void f2h_kernel(const float* __restrict__ in,
                                                  __half* __restrict__ out, int n4)
{
    int i = blockIdx.x * blockDim.x + threadIdx.x;
    if (i >= n4) return;
    float4 v = ((const float4*)in)[i];
    ((uint2*)out)[i] = make_uint2(packh2(v.x, v.y), packh2(v.z, v.w));
}

#define GS2 72   // smem row stride in halves for BK=64 tiles (64 + 8 pad)

// =============================================================================
// QKV GEMM with fused bias + per-head LayerNorm epilogue. BK=64, 3-stage.
// =============================================================================
__global__ __launch_bounds__(256, 2) void gemm_qkv_ln(
    const __half* __restrict__ A, const __half* __restrict__ W,
    const float* __restrict__ bias,
    const float* __restrict__ qw, const float* __restrict__ qb,
    const float* __restrict__ kw, const float* __restrict__ kb,
    __half* __restrict__ Qo, __half* __restrict__ Ko, __half* __restrict__ Vo)
{
    extern __shared__ __half sg[];
    __half* As = sg;                   // [3][128][GS2]
    __half* Bs = sg + 3 * 128 * GS2;   // [3][128][GS2]

    const int K = C_;
    const int tid  = threadIdx.x;
    const int warp = tid >> 5, lane = tid & 31;
    const int mw   = warp >> 1, nw = warp & 1;      // 4 x 2 warp grid
    const int g    = lane >> 2, tg = lane & 3;
    const int bm   = blockIdx.y * 128, bn = blockIdx.x * 128;

    const int aR = (lane & 7) + ((lane >> 3) & 1) * 8;
    const int aC = (lane >> 4) * 8;
    const int bR = (lane & 7) + (lane >> 4) * 8;
    const int bC = ((lane >> 3) & 1) * 8;

    const int lrow = tid >> 3;            // 0..31
    const int lc8  = (tid & 7) * 8;       // 0..56

    const __half* Ap = A + (size_t)bm * K;
    const __half* Wp = W + (size_t)bn * K;

    const int T = K / 64;                 // 16 iterations

    auto issue = [&](int it) {
        const int st = it % 3;
        __half* as = As + st * 128 * GS2;
        __half* bs = Bs + st * 128 * GS2;
        #pragma unroll
        for (int j = 0; j < 4; j++) {
            const int row = lrow + 32 * j;
            CP_ASYNC16(saddr(&as[row * GS2 + lc8]), Ap + (size_t)row * K + it * 64 + lc8);
            CP_ASYNC16(saddr(&bs[row * GS2 + lc8]), Wp + (size_t)row * K + it * 64 + lc8);
        }
        CP_COMMIT();
    };

    float acc[2][8][4];
    #pragma unroll
    for (int i = 0; i < 2; i++)
        #pragma unroll
        for (int j = 0; j < 8; j++)
            #pragma unroll
            for (int e = 0; e < 4; e++) acc[i][j][e] = 0.f;

    issue(0);
    issue(1);

    for (int it = 0; it < T; it++) {
        if (it < T - 1) { CP_WAIT(1); } else { CP_WAIT(0); }
        __syncthreads();
        if (it + 2 < T) issue(it + 2);

        const int st = it % 3;
        __half* as = As + st * 128 * GS2;
        __half* bs = Bs + st * 128 * GS2;

        #pragma unroll
        for (int ks = 0; ks < 4; ks++) {
            const int kk = ks * 16;
            uint32_t a[2][4], b[8][2];
            #pragma unroll
            for (int mt = 0; mt < 2; mt++)
                LDSM_X4(a[mt][0], a[mt][1], a[mt][2], a[mt][3],
                        saddr(&as[(mw * 32 + mt * 16 + aR) * GS2 + kk + aC]));
            #pragma unroll
            for (int np = 0; np < 4; np++) {
                uint32_t r0, r1, r2, r3;
                LDSM_X4(r0, r1, r2, r3,
                        saddr(&bs[(nw * 64 + np * 16 + bR) * GS2 + kk + bC]));
                b[2*np][0] = r0; b[2*np][1] = r1;
                b[2*np+1][0] = r2; b[2*np+1][1] = r3;
            }
            #pragma unroll
            for (int mt = 0; mt < 2; mt++)
                #pragma unroll
                for (int nt = 0; nt < 8; nt++)
                    mma16(acc[mt][nt], a[mt], b[nt]);
        }
    }

    const int cn0 = bn + nw * 64;
    const int sec = cn0 >> 10;             // 0=q, 1=k, 2=v
    const int h   = (cn0 >> 6) & 15;

    float bz[16];
    #pragma unroll
    for (int nt = 0; nt < 8; nt++) {
        bz[2*nt]   = bias[cn0 + nt*8 + 2*tg];
        bz[2*nt+1] = bias[cn0 + nt*8 + 2*tg + 1];
    }
    float lnw[16], lnb[16];
    if (sec < 2) {
        const float* ws = (sec == 0) ? qw : kw;
        const float* bs2 = (sec == 0) ? qb : kb;
        #pragma unroll
        for (int nt = 0; nt < 8; nt++) {
            lnw[2*nt]   = ws[nt*8 + 2*tg];
            lnw[2*nt+1] = ws[nt*8 + 2*tg + 1];
            lnb[2*nt]   = bs2[nt*8 + 2*tg];
            lnb[2*nt+1] = bs2[nt*8 + 2*tg + 1];
        }
    }
    __half* dst = (sec == 0) ? Qo : (sec == 1) ? Ko : Vo;
    const float osc = (sec == 0) ? 0.125f * 1.44269504f : 1.0f;
    const float inv64 = 1.f / 64.f;

    #pragma unroll
    for (int mt = 0; mt < 2; mt++) {
        #pragma unroll
        for (int hh = 0; hh < 2; hh++) {
            const int grow = bm + mw * 32 + mt * 16 + hh * 8 + g;
            float v[16];
            float s = 0.f, ss = 0.f;
            #pragma unroll
            for (int nt = 0; nt < 8; nt++) {
                v[2*nt]   = acc[mt][nt][2*hh]     + bz[2*nt];
                v[2*nt+1] = acc[mt][nt][2*hh + 1] + bz[2*nt+1];
                s  += v[2*nt] + v[2*nt+1];
                ss += v[2*nt]*v[2*nt] + v[2*nt+1]*v[2*nt+1];
            }
            uint32_t outv[8];
            if (sec < 2) {
                s  += __shfl_xor_sync(0xffffffffu, s, 1);
                s  += __shfl_xor_sync(0xffffffffu, s, 2);
                ss += __shfl_xor_sync(0xffffffffu, ss, 1);
                ss += __shfl_xor_sync(0xffffffffu, ss, 2);
                const float mu = s * inv64;
                const float var = fmaxf(ss * inv64 - mu * mu, 0.f);
                const float rstd = rsqrtf(var + 1e-5f);
                #pragma unroll
                for (int nt = 0; nt < 8; nt++) {
                    float o0 = ((v[2*nt]   - mu) * rstd * lnw[2*nt]   + lnb[2*nt])   * osc;
                    float o1 = ((v[2*nt+1] - mu) * rstd * lnw[2*nt+1] + lnb[2*nt+1]) * osc;
                    outv[nt] = packh2(o0, o1);
                }
            } else {
                #pragma unroll
                for (int nt = 0; nt < 8; nt++)
                    outv[nt] = packh2(v[2*nt], v[2*nt+1]);
            }
            const int bb = grow >> 12, n = grow & (N_ - 1);
            __half* op = dst + ((size_t)((bb * H_ + h) * N_) + n) * D_ + 2 * tg;
            #pragma unroll
            for (int nt = 0; nt < 8; nt++)
                *(uint32_t*)(op + nt * 8) = outv[nt];
        }
    }
}

// =============================================================================
// fp16 GEMM for the output projection. BK=64, 3-stage, 2x4 warps.
// =============================================================================
__global__ __launch_bounds__(256, 2) void gemm_h16(
    const __half* __restrict__ A, const __half* __restrict__ W,
    const float* __restrict__ bias, float* __restrict__ Cmat,
    int M, int Nout, int K)
{
    extern __shared__ __half sg[];
    __half* As = sg;
    __half* Bs = sg + 3 * 128 * GS2;

    const int tid  = threadIdx.x;
    const int warp = tid >> 5, lane = tid & 31;
    const int mw   = warp >> 2, nw = warp & 3;
    const int g    = lane >> 2, tg = lane & 3;
    const int bm   = blockIdx.y * 128, bn = blockIdx.x * 128;

    const int aR = (lane & 7) + ((lane >> 3) & 1) * 8;
    const int aC = (lane >> 4) * 8;
    const int bR = (lane & 7) + (lane >> 4) * 8;
    const int bC = ((lane >> 3) & 1) * 8;

    const int lrow = tid >> 3;
    const int lc8  = (tid & 7) * 8;

    const __half* Ap = A + (size_t)bm * K;
    const __half* Wp = W + (size_t)bn * K;

    const int T = K / 64;

    auto issue = [&](int it) {
        const int st = it % 3;
        __half* as = As + st * 128 * GS2;
        __half* bs = Bs + st * 128 * GS2;
        #pragma unroll
        for (int j = 0; j < 4; j++) {
            const int row = lrow + 32 * j;
            CP_ASYNC16(saddr(&as[row * GS2 + lc8]), Ap + (size_t)row * K + it * 64 + lc8);
            CP_ASYNC16(saddr(&bs[row * GS2 + lc8]), Wp + (size_t)row * K + it * 64 + lc8);
        }
        CP_COMMIT();
    };

    float acc[4][4][4];
    #pragma unroll
    for (int i = 0; i < 4; i++)
        #pragma unroll
        for (int j = 0; j < 4; j++)
            #pragma unroll
            for (int e = 0; e < 4; e++) acc[i][j][e] = 0.f;

    issue(0);
    issue(1);

    for (int it = 0; it < T; it++) {
        if (it < T - 1) { CP_WAIT(1); } else { CP_WAIT(0); }
        __syncthreads();
        if (it + 2 < T) issue(it + 2);

        const int st = it % 3;
        __half* as = As + st * 128 * GS2;
        __half* bs = Bs + st * 128 * GS2;

        #pragma unroll
        for (int ks = 0; ks < 4; ks++) {
            const int kk = ks * 16;
            uint32_t a[4][4], b[4][2];
            #pragma unroll
            for (int mt = 0; mt < 4; mt++)
                LDSM_X4(a[mt][0], a[mt][1], a[mt][2], a[mt][3],
                        saddr(&as[(mw * 64 + mt * 16 + aR) * GS2 + kk + aC]));
            #pragma unroll
            for (int np = 0; np < 2; np++) {
                uint32_t r0, r1, r2, r3;
                LDSM_X4(r0, r1, r2, r3,
                        saddr(&bs[(nw * 32 + np * 16 + bR) * GS2 + kk + bC]));
                b[2*np][0] = r0; b[2*np][1] = r1;
                b[2*np+1][0] = r2; b[2*np+1][1] = r3;
            }
            #pragma unroll
            for (int mt = 0; mt < 4; mt++)
                #pragma unroll
                for (int nt = 0; nt < 4; nt++)
                    mma16(acc[mt][nt], a[mt], b[nt]);
        }
    }

    #pragma unroll
    for (int mt = 0; mt < 4; mt++) {
        const int row0 = bm + mw * 64 + mt * 16 + g;
        #pragma unroll
        for (int nt = 0; nt < 4; nt++) {
            const int col = bn + nw * 32 + nt * 8 + 2 * tg;
            const float b0 = bias[col], b1 = bias[col + 1];
            *(float2*)(Cmat + (size_t)row0 * Nout + col) =
                make_float2(acc[mt][nt][0] + b0, acc[mt][nt][1] + b1);
            *(float2*)(Cmat + (size_t)(row0 + 8) * Nout + col) =
                make_float2(acc[mt][nt][2] + b0, acc[mt][nt][3] + b1);
        }
    }
}

// =============================================================================
// Flash attention: 128 q-rows/CTA, 4 warps x 32 rows (128 threads).
// Halves smem crossbar traffic per FLOP: each K/V fragment feeds 2 M-tiles.
// fp16-acc S (zero-conversion softmax), pair-processed 4-stage K/V pipeline,
// l via ones-MMA. 2 CTAs/SM.
// =============================================================================
#define AST2 72

__global__ __launch_bounds__(128, 2) void attn_h16(
    const __half* __restrict__ Q, const __half* __restrict__ Kg,
    const __half* __restrict__ Vg, __half* __restrict__ AO)
{
    extern __shared__ __half sh[];
    __half* Qs = sh;                      // [128][AST2]
    __half* Ks = Qs + 128 * AST2;         // [4][64][AST2]
    __half* Vs = Ks + 4 * 64 * AST2;      // [4][64][AST2]

    const int tid  = threadIdx.x;
    const int warp = tid >> 5, lane = tid & 31;
    const int g    = lane >> 2, tg = lane & 3;
    const int bh   = blockIdx.y;
    const int q0   = blockIdx.x * 128;
    const int mrow = warp * 32;

    const int aR = (lane & 7) + ((lane >> 3) & 1) * 8;
    const int aC = (lane >> 4) * 8;
    const int bR = (lane & 7) + (lane >> 4) * 8;
    const int bC = ((lane >> 3) & 1) * 8;

    const __half* Qb = Q  + ((size_t)bh * N_ + q0) * D_;
    const __half* Kb = Kg + (size_t)bh * N_ * D_;
    const __half* Vb = Vg + (size_t)bh * N_ * D_;

    // ---- load Q tile (128x64 halves): 1024 chunks over 128 threads ----
    #pragma unroll
    for (int j = 0; j < 8; j++) {
        const int id  = tid + 128 * j;
        const int row = id >> 3;
        const int c8  = (id & 7) * 8;
        *(uint4*)&Qs[row * AST2 + c8] = *(const uint4*)(Qb + (size_t)row * D_ + c8);
    }

    auto issueKV = [&](int t) {
        const int st = t & 3;
        #pragma unroll
        for (int j = 0; j < 4; j++) {
            const int id  = tid + 128 * j;
            const int row = id >> 3;
            const int c8  = (id & 7) * 8;
            CP_ASYNC16(saddr(&Ks[(st * 64 + row) * AST2 + c8]),
                       Kb + (size_t)(t * 64 + row) * D_ + c8);
            CP_ASYNC16(saddr(&Vs[(st * 64 + row) * AST2 + c8]),
                       Vb + (size_t)(t * 64 + row) * D_ + c8);
        }
        CP_COMMIT();
    };

    // prime pair 0 (tiles 0,1)
    issueKV(0);
    issueKV(1);
    __syncthreads();   // Q stores visible

    // ---- Q fragments: 2 M-tiles x 4 k-steps ----
    uint32_t qf[2][4][4];
    #pragma unroll
    for (int mt = 0; mt < 2; mt++)
        #pragma unroll
        for (int ks = 0; ks < 4; ks++)
            LDSM_X4(qf[mt][ks][0], qf[mt][ks][1], qf[mt][ks][2], qf[mt][ks][3],
                    saddr(&Qs[(mrow + mt * 16 + aR) * AST2 + ks * 16 + aC]));

    float o[2][8][4];
    #pragma unroll
    for (int mt = 0; mt < 2; mt++)
        #pragma unroll
        for (int nt = 0; nt < 8; nt++)
            #pragma unroll
            for (int e = 0; e < 4; e++) o[mt][nt][e] = 0.f;
    float lacc[2][4] = { { 0.f, 0.f, 0.f, 0.f }, { 0.f, 0.f, 0.f, 0.f } };
    const uint32_t bones[2] = { 0x3C003C00u, 0x3C003C00u };

    const int P = N_ / 128;   // 32 pairs of key tiles
    for (int p = 0; p < P; p++) {
        CP_WAIT(0);           // pair p arrived
        __syncthreads();
        if (p + 1 < P) {
            issueKV(2 * p + 2);
            issueKV(2 * p + 3);
        }

        #pragma unroll
        for (int half = 0; half < 2; half++) {
            const int t  = 2 * p + half;
            const int st = t & 3;
            const __half* Kc = Ks + st * 64 * AST2;
            const __half* Vc = Vs + st * 64 * AST2;

            // ---- S = Q @ K^T, fp16 acc; each K frag feeds both M-tiles ----
            uint32_t sh_acc[2][8][2];
            #pragma unroll
            for (int mt = 0; mt < 2; mt++)
                #pragma unroll
                for (int nt = 0; nt < 8; nt++) {
                    sh_acc[mt][nt][0] = 0u; sh_acc[mt][nt][1] = 0u;
                }

            #pragma unroll
            for (int ks = 0; ks < 4; ks++) {
                const int kk = ks * 16;
                #pragma unroll
                for (int np = 0; np < 4; np++) {
                    uint32_t r0, r1, r2, r3;
                    LDSM_X4(r0, r1, r2, r3,
                            saddr(&Kc[(np * 16 + bR) * AST2 + kk + bC]));
                    uint32_t b0[2] = { r0, r1 }, b1[2] = { r2, r3 };
                    #pragma unroll
                    for (int mt = 0; mt < 2; mt++) {
                        mma16h(sh_acc[mt][2*np],     qf[mt][ks], b0);
                        mma16h(sh_acc[mt][2*np + 1], qf[mt][ks], b1);
                    }
                }
            }

            // ---- p = exp2(s) in-place on f16x2 accumulators ----
            #pragma unroll
            for (int mt = 0; mt < 2; mt++)
                #pragma unroll
                for (int nt = 0; nt < 8; nt++) {
                    asm("ex2.approx.f16x2 %0, %0;" : "+r"(sh_acc[mt][nt][0]));
                    asm("ex2.approx.f16x2 %0, %0;" : "+r"(sh_acc[mt][nt][1]));
                }

            // ---- O += P @ V ; l += P @ ones; each V frag feeds both M-tiles ----
            #pragma unroll
            for (int ks = 0; ks < 4; ks++) {
                const int kk = ks * 16;
                uint32_t a0[4] = { sh_acc[0][2*ks][0], sh_acc[0][2*ks][1],
                                   sh_acc[0][2*ks+1][0], sh_acc[0][2*ks+1][1] };
                uint32_t a1[4] = { sh_acc[1][2*ks][0], sh_acc[1][2*ks][1],
                                   sh_acc[1][2*ks+1][0], sh_acc[1][2*ks+1][1] };
                mma16(lacc[0], a0, bones);
                mma16(lacc[1], a1, bones);
                #pragma unroll
                for (int dp = 0; dp < 4; dp++) {
                    uint32_t r0, r1, r2, r3;
                    LDSM_X4T(r0, r1, r2, r3,
                             saddr(&Vc[(kk + aR) * AST2 + dp * 16 + aC]));
                    uint32_t b0[2] = { r0, r1 }, b1[2] = { r2, r3 };
                    mma16(o[0][2*dp],     a0, b0);
                    mma16(o[0][2*dp + 1], a0, b1);
                    mma16(o[1][2*dp],     a1, b0);
                    mma16(o[1][2*dp + 1], a1, b1);
                }
            }
        }
    }

    // ---- epilogue ----
    const int b = bh >> 4, h = bh & 15;
    #pragma unroll
    for (int mt = 0; mt < 2; mt++) {
        const float inv0 = 1.f / lacc[mt][0], inv1 = 1.f / lacc[mt][2];
        __half* op = AO + ((size_t)(b * N_ + q0 + mrow + mt * 16 + g)) * C_ + h * D_;
        #pragma unroll
        for (int nt = 0; nt < 8; nt++) {
            const int col = nt * 8 + 2 * tg;
            *(__half2*)(op + col) =
                __floats2half2_rn(o[mt][nt][0] * inv0, o[mt][nt][1] * inv0);
            *(__half2*)(op + (size_t)8 * C_ + col) =
                __floats2half2_rn(o[mt][nt][2] * inv1, o[mt][nt][3] * inv1);
        }
    }
}

// =============================================================================
extern "C" void kernel_launch(void* const* d_in, const int* in_sizes, int n_in,
                              void* d_out, int out_size)
{
    const float* x      = (const float*)d_in[0];
    const float* qkv_w  = (const float*)d_in[1];
    const float* qkv_b  = (const float*)d_in[2];
    const float* qnw    = (const float*)d_in[3];
    const float* qnb    = (const float*)d_in[4];
    const float* knw    = (const float*)d_in[5];
    const float* knb    = (const float*)d_in[6];
    const float* proj_w = (const float*)d_in[7];
    const float* proj_b = (const float*)d_in[8];
    float* out = (float*)d_out;

    __half *xh, *wqkv, *wproj, *q, *k, *v, *ao;
    cudaGetSymbolAddress((void**)&xh,    g_xh);
    cudaGetSymbolAddress((void**)&wqkv,  g_wqkv_h);
    cudaGetSymbolAddress((void**)&wproj, g_wproj_h);
    cudaGetSymbolAddress((void**)&q,     g_q);
    cudaGetSymbolAddress((void**)&k,     g_k);
    cudaGetSymbolAddress((void**)&v,     g_v);
    cudaGetSymbolAddress((void**)&ao,    g_ao);

    const int gemm_smem = 2 * 3 * 128 * GS2 * (int)sizeof(__half);     // 110592
    const int attn_smem = (128 + 8 * 64) * AST2 * (int)sizeof(__half); // 92160
    cudaFuncSetAttribute(gemm_h16, cudaFuncAttributeMaxDynamicSharedMemorySize, gemm_smem);
    cudaFuncSetAttribute(gemm_qkv_ln, cudaFuncAttributeMaxDynamicSharedMemorySize, gemm_smem);
    cudaFuncSetAttribute(attn_h16, cudaFuncAttributeMaxDynamicSharedMemorySize, attn_smem);

    // 0) fp16 preconversion
    {
        int n4x = (B_ * N_ * C_) / 4;
        f2h_kernel<<<(n4x + 255) / 256, 256>>>(x, xh, n4x);
        int n4w = (3 * C_ * C_) / 4;
        f2h_kernel<<<(n4w + 255) / 256, 256>>>(qkv_w, wqkv, n4w);
        int n4p = (C_ * C_) / 4;
        f2h_kernel<<<(n4p + 255) / 256, 256>>>(proj_w, wproj, n4p);
    }
    // 1) QKV projection + fused bias/LN/split
    {
        dim3 grid(3 * C_ / 128, (B_ * N_) / 128);
        gemm_qkv_ln<<<grid, 256, gemm_smem>>>(xh, wqkv, qkv_b,
                                              qnw, qnb, knw, knb, q, k, v);
    }
    // 2) attention (4 warps x 32 rows, halved smem traffic)
    {
        dim3 grid(N_ / 128, BH_);
        attn_h16<<<grid, 128, attn_smem>>>(q, k, v, ao);
    }
    // 3) output projection -> d_out
    {
        dim3 grid(C_ / 128, (B_ * N_) / 128);
        gemm_h16<<<grid, 256, gemm_smem>>>(ao, wproj, proj_b, out, B_ * N_, C_, C_);
    }
}

// round 16
// speedup vs baseline: 1.8392x; 1.0066x over previous
#include <cuda_runtime.h>
#include <cuda_fp16.h>
#include <math.h>
#include <stdint.h>
#include <stddef.h>

#define B_  2
#define N_  4096
#define C_  1024
#define H_  16
#define D_  64
#define BH_ (B_*H_)

// ---------------- scratch (device globals; no allocs allowed) ----------------
__device__ __half g_xh    [(size_t)B_*N_*C_];     // x in fp16
__device__ __half g_wqkv_h[(size_t)3*C_*C_];      // qkv_w fp16
__device__ __half g_wproj_h[(size_t)C_*C_];       // proj_w fp16
__device__ __half g_q [(size_t)BH_*N_*D_];        // LN'd, pre-scaled by 0.125*log2e
__device__ __half g_k [(size_t)BH_*N_*D_];
__device__ __half g_v [(size_t)BH_*N_*D_];
__device__ __half g_ao[(size_t)B_*N_*C_];         // [B,N,C] attention out fp16

// ---------------- helpers ----------------
__device__ __forceinline__ uint32_t packh2(float x, float y) {
    __half2 h = __floats2half2_rn(x, y);
    return *(uint32_t*)&h;
}
__device__ __forceinline__ uint32_t saddr(const void* p) {
    return (uint32_t)__cvta_generic_to_shared(p);
}

__device__ __forceinline__ void mma16(float* c, const uint32_t* a, const uint32_t* b) {
    asm volatile(
        "mma.sync.aligned.m16n8k16.row.col.f32.f16.f16.f32 "
        "{%0,%1,%2,%3}, {%4,%5,%6,%7}, {%8,%9}, {%0,%1,%2,%3};"
        : "+f"(c[0]), "+f"(c[1]), "+f"(c[2]), "+f"(c[3])
        : "r"(a[0]), "r"(a[1]), "r"(a[2]), "r"(a[3]), "r"(b[0]), "r"(b[1]));
}

// fp16-accumulator variant: C/D = 2x f16x2 regs (row g | row g+8, cols 2tg,2tg+1)
__device__ __forceinline__ void mma16h(uint32_t* c, const uint32_t* a, const uint32_t* b) {
    asm volatile(
        "mma.sync.aligned.m16n8k16.row.col.f16.f16.f16.f16 "
        "{%0,%1}, {%2,%3,%4,%5}, {%6,%7}, {%0,%1};"
        : "+r"(c[0]), "+r"(c[1])
        : "r"(a[0]), "r"(a[1]), "r"(a[2]), "r"(a[3]), "r"(b[0]), "r"(b[1]));
}

#define LDSM_X4(R0,R1,R2,R3,ADDR) \
    asm volatile("ldmatrix.sync.aligned.m8n8.x4.shared.b16 {%0,%1,%2,%3}, [%4];" \
        : "=r"(R0), "=r"(R1), "=r"(R2), "=r"(R3) : "r"(ADDR))
#define LDSM_X4T(R0,R1,R2,R3,ADDR) \
    asm volatile("ldmatrix.sync.aligned.m8n8.x4.trans.shared.b16 {%0,%1,%2,%3}, [%4];" \
        : "=r"(R0), "=r"(R1), "=r"(R2), "=r"(R3) : "r"(ADDR))

#define CP_ASYNC16(dst_u32, src) \
    asm volatile("cp.async.cg.shared.global [%0], [%1], 16;" :: "r"(dst_u32), "l"(src))
#define CP_COMMIT() asm volatile("cp.async.commit_group;")
#define CP_WAIT(n)  asm volatile("cp.async.wait_group %0;" :: "n"(n))

// =============================================================================
// fp32 -> fp16 elementwise convert
// =============================================================================
__global__ __launch_bounds__(256) void f2h_kernel(const float* __restrict__ in,
                                                  __half* __restrict__ out, int n4)
{
    int i = blockIdx.x * blockDim.x + threadIdx.x;
    if (i >= n4) return;
    float4 v = ((const float4*)in)[i];
    ((uint2*)out)[i] = make_uint2(packh2(v.x, v.y), packh2(v.z, v.w));
}

#define GS2 72   // smem row stride in halves for BK=64 tiles (64 + 8 pad)

// =============================================================================
// QKV GEMM + fused bias/per-head-LN epilogue. 128 threads, 2x2 warp grid,
// 64x64 warp tiles (4 MMA per ldsm). BK=64, 3-stage cp.async.
// =============================================================================
__global__ __launch_bounds__(128, 2) void gemm_qkv_ln(
    const __half* __restrict__ A, const __half* __restrict__ W,
    const float* __restrict__ bias,
    const float* __restrict__ qw, const float* __restrict__ qb,
    const float* __restrict__ kw, const float* __restrict__ kb,
    __half* __restrict__ Qo, __half* __restrict__ Ko, __half* __restrict__ Vo)
{
    extern __shared__ __half sg[];
    __half* As = sg;                   // [3][128][GS2]
    __half* Bs = sg + 3 * 128 * GS2;   // [3][128][GS2]

    const int K = C_;
    const int tid  = threadIdx.x;
    const int warp = tid >> 5, lane = tid & 31;
    const int mw   = warp >> 1, nw = warp & 1;      // 2 x 2 warp grid
    const int g    = lane >> 2, tg = lane & 3;
    const int bm   = blockIdx.y * 128, bn = blockIdx.x * 128;

    const int aR = (lane & 7) + ((lane >> 3) & 1) * 8;
    const int aC = (lane >> 4) * 8;
    const int bR = (lane & 7) + (lane >> 4) * 8;
    const int bC = ((lane >> 3) & 1) * 8;

    const int lrow = tid >> 3;            // 0..15
    const int lc8  = (tid & 7) * 8;       // 0..56

    const __half* Ap = A + (size_t)bm * K;
    const __half* Wp = W + (size_t)bn * K;

    const int T = K / 64;                 // 16 iterations

    auto issue = [&](int it) {
        const int st = it % 3;
        __half* as = As + st * 128 * GS2;
        __half* bs = Bs + st * 128 * GS2;
        #pragma unroll
        for (int j = 0; j < 8; j++) {
            const int row = lrow + 16 * j;
            CP_ASYNC16(saddr(&as[row * GS2 + lc8]), Ap + (size_t)row * K + it * 64 + lc8);
            CP_ASYNC16(saddr(&bs[row * GS2 + lc8]), Wp + (size_t)row * K + it * 64 + lc8);
        }
        CP_COMMIT();
    };

    float acc[4][8][4];
    #pragma unroll
    for (int i = 0; i < 4; i++)
        #pragma unroll
        for (int j = 0; j < 8; j++)
            #pragma unroll
            for (int e = 0; e < 4; e++) acc[i][j][e] = 0.f;

    issue(0);
    issue(1);

    for (int it = 0; it < T; it++) {
        if (it < T - 1) { CP_WAIT(1); } else { CP_WAIT(0); }
        __syncthreads();
        if (it + 2 < T) issue(it + 2);

        const int st = it % 3;
        __half* as = As + st * 128 * GS2;
        __half* bs = Bs + st * 128 * GS2;

        #pragma unroll
        for (int ks = 0; ks < 4; ks++) {
            const int kk = ks * 16;
            uint32_t a[4][4], b[8][2];
            #pragma unroll
            for (int mt = 0; mt < 4; mt++)
                LDSM_X4(a[mt][0], a[mt][1], a[mt][2], a[mt][3],
                        saddr(&as[(mw * 64 + mt * 16 + aR) * GS2 + kk + aC]));
            #pragma unroll
            for (int np = 0; np < 4; np++) {
                uint32_t r0, r1, r2, r3;
                LDSM_X4(r0, r1, r2, r3,
                        saddr(&bs[(nw * 64 + np * 16 + bR) * GS2 + kk + bC]));
                b[2*np][0] = r0; b[2*np][1] = r1;
                b[2*np+1][0] = r2; b[2*np+1][1] = r3;
            }
            #pragma unroll
            for (int mt = 0; mt < 4; mt++)
                #pragma unroll
                for (int nt = 0; nt < 8; nt++)
                    mma16(acc[mt][nt], a[mt], b[nt]);
        }
    }

    // ---- fused epilogue: bias + (LN for q/k) + fp16 write; warp owns 1 head ----
    const int cn0 = bn + nw * 64;
    const int sec = cn0 >> 10;             // 0=q, 1=k, 2=v
    const int h   = (cn0 >> 6) & 15;

    float bz[16];
    #pragma unroll
    for (int nt = 0; nt < 8; nt++) {
        bz[2*nt]   = bias[cn0 + nt*8 + 2*tg];
        bz[2*nt+1] = bias[cn0 + nt*8 + 2*tg + 1];
    }
    float lnw[16], lnb[16];
    if (sec < 2) {
        const float* ws = (sec == 0) ? qw : kw;
        const float* bs2 = (sec == 0) ? qb : kb;
        #pragma unroll
        for (int nt = 0; nt < 8; nt++) {
            lnw[2*nt]   = ws[nt*8 + 2*tg];
            lnw[2*nt+1] = ws[nt*8 + 2*tg + 1];
            lnb[2*nt]   = bs2[nt*8 + 2*tg];
            lnb[2*nt+1] = bs2[nt*8 + 2*tg + 1];
        }
    }
    __half* dst = (sec == 0) ? Qo : (sec == 1) ? Ko : Vo;
    const float osc = (sec == 0) ? 0.125f * 1.44269504f : 1.0f;
    const float inv64 = 1.f / 64.f;

    #pragma unroll
    for (int mt = 0; mt < 4; mt++) {
        #pragma unroll
        for (int hh = 0; hh < 2; hh++) {
            const int grow = bm + mw * 64 + mt * 16 + hh * 8 + g;
            float v[16];
            float s = 0.f, ss = 0.f;
            #pragma unroll
            for (int nt = 0; nt < 8; nt++) {
                v[2*nt]   = acc[mt][nt][2*hh]     + bz[2*nt];
                v[2*nt+1] = acc[mt][nt][2*hh + 1] + bz[2*nt+1];
                s  += v[2*nt] + v[2*nt+1];
                ss += v[2*nt]*v[2*nt] + v[2*nt+1]*v[2*nt+1];
            }
            uint32_t outv[8];
            if (sec < 2) {
                s  += __shfl_xor_sync(0xffffffffu, s, 1);
                s  += __shfl_xor_sync(0xffffffffu, s, 2);
                ss += __shfl_xor_sync(0xffffffffu, ss, 1);
                ss += __shfl_xor_sync(0xffffffffu, ss, 2);
                const float mu = s * inv64;
                const float var = fmaxf(ss * inv64 - mu * mu, 0.f);
                const float rstd = rsqrtf(var + 1e-5f);
                #pragma unroll
                for (int nt = 0; nt < 8; nt++) {
                    float o0 = ((v[2*nt]   - mu) * rstd * lnw[2*nt]   + lnb[2*nt])   * osc;
                    float o1 = ((v[2*nt+1] - mu) * rstd * lnw[2*nt+1] + lnb[2*nt+1]) * osc;
                    outv[nt] = packh2(o0, o1);
                }
            } else {
                #pragma unroll
                for (int nt = 0; nt < 8; nt++)
                    outv[nt] = packh2(v[2*nt], v[2*nt+1]);
            }
            const int bb = grow >> 12, n = grow & (N_ - 1);
            __half* op = dst + ((size_t)((bb * H_ + h) * N_) + n) * D_ + 2 * tg;
            #pragma unroll
            for (int nt = 0; nt < 8; nt++)
                *(uint32_t*)(op + nt * 8) = outv[nt];
        }
    }
}

// =============================================================================
// Output-projection GEMM. 128 threads, 2x2 warp grid, 64x64 warp tiles.
// =============================================================================
__global__ __launch_bounds__(128, 2) void gemm_h16(
    const __half* __restrict__ A, const __half* __restrict__ W,
    const float* __restrict__ bias, float* __restrict__ Cmat,
    int M, int Nout, int K)
{
    extern __shared__ __half sg[];
    __half* As = sg;
    __half* Bs = sg + 3 * 128 * GS2;

    const int tid  = threadIdx.x;
    const int warp = tid >> 5, lane = tid & 31;
    const int mw   = warp >> 1, nw = warp & 1;
    const int g    = lane >> 2, tg = lane & 3;
    const int bm   = blockIdx.y * 128, bn = blockIdx.x * 128;

    const int aR = (lane & 7) + ((lane >> 3) & 1) * 8;
    const int aC = (lane >> 4) * 8;
    const int bR = (lane & 7) + (lane >> 4) * 8;
    const int bC = ((lane >> 3) & 1) * 8;

    const int lrow = tid >> 3;
    const int lc8  = (tid & 7) * 8;

    const __half* Ap = A + (size_t)bm * K;
    const __half* Wp = W + (size_t)bn * K;

    const int T = K / 64;

    auto issue = [&](int it) {
        const int st = it % 3;
        __half* as = As + st * 128 * GS2;
        __half* bs = Bs + st * 128 * GS2;
        #pragma unroll
        for (int j = 0; j < 8; j++) {
            const int row = lrow + 16 * j;
            CP_ASYNC16(saddr(&as[row * GS2 + lc8]), Ap + (size_t)row * K + it * 64 + lc8);
            CP_ASYNC16(saddr(&bs[row * GS2 + lc8]), Wp + (size_t)row * K + it * 64 + lc8);
        }
        CP_COMMIT();
    };

    float acc[4][8][4];
    #pragma unroll
    for (int i = 0; i < 4; i++)
        #pragma unroll
        for (int j = 0; j < 8; j++)
            #pragma unroll
            for (int e = 0; e < 4; e++) acc[i][j][e] = 0.f;

    issue(0);
    issue(1);

    for (int it = 0; it < T; it++) {
        if (it < T - 1) { CP_WAIT(1); } else { CP_WAIT(0); }
        __syncthreads();
        if (it + 2 < T) issue(it + 2);

        const int st = it % 3;
        __half* as = As + st * 128 * GS2;
        __half* bs = Bs + st * 128 * GS2;

        #pragma unroll
        for (int ks = 0; ks < 4; ks++) {
            const int kk = ks * 16;
            uint32_t a[4][4], b[8][2];
            #pragma unroll
            for (int mt = 0; mt < 4; mt++)
                LDSM_X4(a[mt][0], a[mt][1], a[mt][2], a[mt][3],
                        saddr(&as[(mw * 64 + mt * 16 + aR) * GS2 + kk + aC]));
            #pragma unroll
            for (int np = 0; np < 4; np++) {
                uint32_t r0, r1, r2, r3;
                LDSM_X4(r0, r1, r2, r3,
                        saddr(&bs[(nw * 64 + np * 16 + bR) * GS2 + kk + bC]));
                b[2*np][0] = r0; b[2*np][1] = r1;
                b[2*np+1][0] = r2; b[2*np+1][1] = r3;
            }
            #pragma unroll
            for (int mt = 0; mt < 4; mt++)
                #pragma unroll
                for (int nt = 0; nt < 8; nt++)
                    mma16(acc[mt][nt], a[mt], b[nt]);
        }
    }

    #pragma unroll
    for (int mt = 0; mt < 4; mt++) {
        const int row0 = bm + mw * 64 + mt * 16 + g;
        #pragma unroll
        for (int nt = 0; nt < 8; nt++) {
            const int col = bn + nw * 64 + nt * 8 + 2 * tg;
            const float b0 = bias[col], b1 = bias[col + 1];
            *(float2*)(Cmat + (size_t)row0 * Nout + col) =
                make_float2(acc[mt][nt][0] + b0, acc[mt][nt][1] + b1);
            *(float2*)(Cmat + (size_t)(row0 + 8) * Nout + col) =
                make_float2(acc[mt][nt][2] + b0, acc[mt][nt][3] + b1);
        }
    }
}

// =============================================================================
// Flash attention (proven R15): 128 q-rows/CTA, 4 warps x 32 rows.
// fp16-acc S, pair-processed 4-stage K/V pipeline, l via ones-MMA. 2 CTAs/SM.
// =============================================================================
#define AST2 72

__global__ __launch_bounds__(128, 2) void attn_h16(
    const __half* __restrict__ Q, const __half* __restrict__ Kg,
    const __half* __restrict__ Vg, __half* __restrict__ AO)
{
    extern __shared__ __half sh[];
    __half* Qs = sh;                      // [128][AST2]
    __half* Ks = Qs + 128 * AST2;         // [4][64][AST2]
    __half* Vs = Ks + 4 * 64 * AST2;      // [4][64][AST2]

    const int tid  = threadIdx.x;
    const int warp = tid >> 5, lane = tid & 31;
    const int g    = lane >> 2, tg = lane & 3;
    const int bh   = blockIdx.y;
    const int q0   = blockIdx.x * 128;
    const int mrow = warp * 32;

    const int aR = (lane & 7) + ((lane >> 3) & 1) * 8;
    const int aC = (lane >> 4) * 8;
    const int bR = (lane & 7) + (lane >> 4) * 8;
    const int bC = ((lane >> 3) & 1) * 8;

    const __half* Qb = Q  + ((size_t)bh * N_ + q0) * D_;
    const __half* Kb = Kg + (size_t)bh * N_ * D_;
    const __half* Vb = Vg + (size_t)bh * N_ * D_;

    // ---- load Q tile (128x64 halves): 1024 chunks over 128 threads ----
    #pragma unroll
    for (int j = 0; j < 8; j++) {
        const int id  = tid + 128 * j;
        const int row = id >> 3;
        const int c8  = (id & 7) * 8;
        *(uint4*)&Qs[row * AST2 + c8] = *(const uint4*)(Qb + (size_t)row * D_ + c8);
    }

    auto issueKV = [&](int t) {
        const int st = t & 3;
        #pragma unroll
        for (int j = 0; j < 4; j++) {
            const int id  = tid + 128 * j;
            const int row = id >> 3;
            const int c8  = (id & 7) * 8;
            CP_ASYNC16(saddr(&Ks[(st * 64 + row) * AST2 + c8]),
                       Kb + (size_t)(t * 64 + row) * D_ + c8);
            CP_ASYNC16(saddr(&Vs[(st * 64 + row) * AST2 + c8]),
                       Vb + (size_t)(t * 64 + row) * D_ + c8);
        }
        CP_COMMIT();
    };

    // prime pair 0 (tiles 0,1)
    issueKV(0);
    issueKV(1);
    __syncthreads();   // Q stores visible

    // ---- Q fragments: 2 M-tiles x 4 k-steps ----
    uint32_t qf[2][4][4];
    #pragma unroll
    for (int mt = 0; mt < 2; mt++)
        #pragma unroll
        for (int ks = 0; ks < 4; ks++)
            LDSM_X4(qf[mt][ks][0], qf[mt][ks][1], qf[mt][ks][2], qf[mt][ks][3],
                    saddr(&Qs[(mrow + mt * 16 + aR) * AST2 + ks * 16 + aC]));

    float o[2][8][4];
    #pragma unroll
    for (int mt = 0; mt < 2; mt++)
        #pragma unroll
        for (int nt = 0; nt < 8; nt++)
            #pragma unroll
            for (int e = 0; e < 4; e++) o[mt][nt][e] = 0.f;
    float lacc[2][4] = { { 0.f, 0.f, 0.f, 0.f }, { 0.f, 0.f, 0.f, 0.f } };
    const uint32_t bones[2] = { 0x3C003C00u, 0x3C003C00u };

    const int P = N_ / 128;   // 32 pairs of key tiles
    for (int p = 0; p < P; p++) {
        CP_WAIT(0);           // pair p arrived
        __syncthreads();
        if (p + 1 < P) {
            issueKV(2 * p + 2);
            issueKV(2 * p + 3);
        }

        #pragma unroll
        for (int half = 0; half < 2; half++) {
            const int t  = 2 * p + half;
            const int st = t & 3;
            const __half* Kc = Ks + st * 64 * AST2;
            const __half* Vc = Vs + st * 64 * AST2;

            // ---- S = Q @ K^T, fp16 acc; each K frag feeds both M-tiles ----
            uint32_t sh_acc[2][8][2];
            #pragma unroll
            for (int mt = 0; mt < 2; mt++)
                #pragma unroll
                for (int nt = 0; nt < 8; nt++) {
                    sh_acc[mt][nt][0] = 0u; sh_acc[mt][nt][1] = 0u;
                }

            #pragma unroll
            for (int ks = 0; ks < 4; ks++) {
                const int kk = ks * 16;
                #pragma unroll
                for (int np = 0; np < 4; np++) {
                    uint32_t r0, r1, r2, r3;
                    LDSM_X4(r0, r1, r2, r3,
                            saddr(&Kc[(np * 16 + bR) * AST2 + kk + bC]));
                    uint32_t b0[2] = { r0, r1 }, b1[2] = { r2, r3 };
                    #pragma unroll
                    for (int mt = 0; mt < 2; mt++) {
                        mma16h(sh_acc[mt][2*np],     qf[mt][ks], b0);
                        mma16h(sh_acc[mt][2*np + 1], qf[mt][ks], b1);
                    }
                }
            }

            // ---- p = exp2(s) in-place on f16x2 accumulators ----
            #pragma unroll
            for (int mt = 0; mt < 2; mt++)
                #pragma unroll
                for (int nt = 0; nt < 8; nt++) {
                    asm("ex2.approx.f16x2 %0, %0;" : "+r"(sh_acc[mt][nt][0]));
                    asm("ex2.approx.f16x2 %0, %0;" : "+r"(sh_acc[mt][nt][1]));
                }

            // ---- O += P @ V ; l += P @ ones; each V frag feeds both M-tiles ----
            #pragma unroll
            for (int ks = 0; ks < 4; ks++) {
                const int kk = ks * 16;
                uint32_t a0[4] = { sh_acc[0][2*ks][0], sh_acc[0][2*ks][1],
                                   sh_acc[0][2*ks+1][0], sh_acc[0][2*ks+1][1] };
                uint32_t a1[4] = { sh_acc[1][2*ks][0], sh_acc[1][2*ks][1],
                                   sh_acc[1][2*ks+1][0], sh_acc[1][2*ks+1][1] };
                mma16(lacc[0], a0, bones);
                mma16(lacc[1], a1, bones);
                #pragma unroll
                for (int dp = 0; dp < 4; dp++) {
                    uint32_t r0, r1, r2, r3;
                    LDSM_X4T(r0, r1, r2, r3,
                             saddr(&Vc[(kk + aR) * AST2 + dp * 16 + aC]));
                    uint32_t b0[2] = { r0, r1 }, b1[2] = { r2, r3 };
                    mma16(o[0][2*dp],     a0, b0);
                    mma16(o[0][2*dp + 1], a0, b1);
                    mma16(o[1][2*dp],     a1, b0);
                    mma16(o[1][2*dp + 1], a1, b1);
                }
            }
        }
    }

    // ---- epilogue ----
    const int b = bh >> 4, h = bh & 15;
    #pragma unroll
    for (int mt = 0; mt < 2; mt++) {
        const float inv0 = 1.f / lacc[mt][0], inv1 = 1.f / lacc[mt][2];
        __half* op = AO + ((size_t)(b * N_ + q0 + mrow + mt * 16 + g)) * C_ + h * D_;
        #pragma unroll
        for (int nt = 0; nt < 8; nt++) {
            const int col = nt * 8 + 2 * tg;
            *(__half2*)(op + col) =
                __floats2half2_rn(o[mt][nt][0] * inv0, o[mt][nt][1] * inv0);
            *(__half2*)(op + (size_t)8 * C_ + col) =
                __floats2half2_rn(o[mt][nt][2] * inv1, o[mt][nt][3] * inv1);
        }
    }
}

// =============================================================================
extern "C" void kernel_launch(void* const* d_in, const int* in_sizes, int n_in,
                              void* d_out, int out_size)
{
    const float* x      = (const float*)d_in[0];
    const float* qkv_w  = (const float*)d_in[1];
    const float* qkv_b  = (const float*)d_in[2];
    const float* qnw    = (const float*)d_in[3];
    const float* qnb    = (const float*)d_in[4];
    const float* knw    = (const float*)d_in[5];
    const float* knb    = (const float*)d_in[6];
    const float* proj_w = (const float*)d_in[7];
    const float* proj_b = (const float*)d_in[8];
    float* out = (float*)d_out;

    __half *xh, *wqkv, *wproj, *q, *k, *v, *ao;
    cudaGetSymbolAddress((void**)&xh,    g_xh);
    cudaGetSymbolAddress((void**)&wqkv,  g_wqkv_h);
    cudaGetSymbolAddress((void**)&wproj, g_wproj_h);
    cudaGetSymbolAddress((void**)&q,     g_q);
    cudaGetSymbolAddress((void**)&k,     g_k);
    cudaGetSymbolAddress((void**)&v,     g_v);
    cudaGetSymbolAddress((void**)&ao,    g_ao);

    const int gemm_smem = 2 * 3 * 128 * GS2 * (int)sizeof(__half);     // 110592
    const int attn_smem = (128 + 8 * 64) * AST2 * (int)sizeof(__half); // 92160
    cudaFuncSetAttribute(gemm_h16, cudaFuncAttributeMaxDynamicSharedMemorySize, gemm_smem);
    cudaFuncSetAttribute(gemm_qkv_ln, cudaFuncAttributeMaxDynamicSharedMemorySize, gemm_smem);
    cudaFuncSetAttribute(attn_h16, cudaFuncAttributeMaxDynamicSharedMemorySize, attn_smem);

    // 0) fp16 preconversion
    {
        int n4x = (B_ * N_ * C_) / 4;
        f2h_kernel<<<(n4x + 255) / 256, 256>>>(x, xh, n4x);
        int n4w = (3 * C_ * C_) / 4;
        f2h_kernel<<<(n4w + 255) / 256, 256>>>(qkv_w, wqkv, n4w);
        int n4p = (C_ * C_) / 4;
        f2h_kernel<<<(n4p + 255) / 256, 256>>>(proj_w, wproj, n4p);
    }
    // 1) QKV projection + fused bias/LN/split (64x64 warp tiles)
    {
        dim3 grid(3 * C_ / 128, (B_ * N_) / 128);
        gemm_qkv_ln<<<grid, 128, gemm_smem>>>(xh, wqkv, qkv_b,
                                              qnw, qnb, knw, knb, q, k, v);
    }
    // 2) attention
    {
        dim3 grid(N_ / 128, BH_);
        attn_h16<<<grid, 128, attn_smem>>>(q, k, v, ao);
    }
    // 3) output projection -> d_out (64x64 warp tiles)
    {
        dim3 grid(C_ / 128, (B_ * N_) / 128);
        gemm_h16<<<grid, 128, gemm_smem>>>(ao, wproj, proj_b, out, B_ * N_, C_, C_);
    }
}